// round 3
// baseline (speedup 1.0000x reference)
#include <cuda_runtime.h>
#include <math.h>

// ---------------------------------------------------------------------------
// Fixed problem shapes
// ---------------------------------------------------------------------------
#define BATCH 2
#define CHN   256
#define NTOT  43095          // anchors per batch across 4 levels
#define TOTC  3507           // top-k candidates per batch (1000+1000+1000+507)
#define POST  300
#define NEGF  (-1e30f)
#define CLAMPF 4.135166556742356f   // log(1000/16)
#define IMG   832.0f

__device__ __constant__ int   c_W[4]      = {104, 52, 26, 13};
__device__ __constant__ int   c_Nanch[4]  = {32448, 8112, 2028, 507};
__device__ __constant__ int   c_noff[4]   = {0, 32448, 40560, 42588};
__device__ __constant__ int   c_K[4]      = {1000, 1000, 1000, 507};
__device__ __constant__ int   c_cbase[4]  = {0, 1000, 2000, 3000};
__device__ __constant__ float c_stride[4] = {8.f, 16.f, 32.f, 64.f};
__device__ __constant__ float c_size[4]   = {32.f, 64.f, 128.f, 256.f};

// ---------------------------------------------------------------------------
// Static device scratch (no dynamic allocation allowed)
// ---------------------------------------------------------------------------
__device__ float g_t[BATCH * CHN * 10816];     // conv+relu output (per level, reused)
__device__ float g_wT[2304 * CHN];             // conv weights, [k][co]
__device__ float g_ft3[BATCH * 169 * CHN];     // feat3 channels-last
__device__ float g_logits[BATCH * NTOT];
__device__ float g_deltas[BATCH * NTOT * 4];
__device__ int   g_cand_n[BATCH * TOTC];       // per-level local anchor index
__device__ float g_sc[BATCH * TOTC];
__device__ float g_box[BATCH * TOTC * 4];      // clipped boxes
__device__ float g_obox[BATCH * TOTC * 4];     // +4096*lvl offset boxes
__device__ float g_rois[BATCH * POST * 4];
__device__ float g_rf[600 * 12544];            // ROI features (FC input)

// ---------------------------------------------------------------------------
// Prep: transpose conv weights to [k][co]; feat3 to channels-last
// ---------------------------------------------------------------------------
__global__ void prep_wT(const float* __restrict__ cw)
{
    int k  = blockIdx.x;       // 0..2303
    int co = threadIdx.x;      // 0..255
    g_wT[k * 256 + co] = cw[co * 2304 + k];
}

__global__ void prep_ft3(const float* __restrict__ f3)
{
    int idx = blockIdx.x * 256 + threadIdx.x;
    if (idx >= BATCH * 169 * 256) return;
    int c = idx & 255;
    int p = (idx >> 8) % 169;
    int b = idx / (169 * 256);
    g_ft3[idx] = f3[(b * 256 + c) * 169 + p];
}

// ---------------------------------------------------------------------------
// Conv 3x3 (+bias, +ReLU) as implicit GEMM:
//   out[co][p] = sum_{k=ci*9+r} wT[k][co] * im2col[k][p]
// Block: 64 co x 64 pixels, 256 threads, 4x4 micro-tile, K-chunk 8.
// ---------------------------------------------------------------------------
__global__ void __launch_bounds__(256) conv3x3_gemm(
    const float* __restrict__ in, const float* __restrict__ bias,
    int H, int W, int Np)
{
    __shared__ __align__(16) float As[8][64];
    __shared__ __align__(16) float Bs[8][64];

    int b   = blockIdx.z;
    int co0 = blockIdx.y * 64;
    int p0  = blockIdx.x * 64;
    int t   = threadIdx.x;
    int tx  = t & 15, ty = t >> 4;
    const float* inb = in + (size_t)b * CHN * H * W;
    int HW = H * W;

    // B-load mapping: each thread owns one pixel (pp), two k-rows (kl, kl+4)
    int pp = t & 63;
    int kl = t >> 6;                 // 0..3
    int pix = p0 + pp;
    bool inp = pix < Np;
    int py = inp ? (pix / W) : 0;
    int px = inp ? (pix - py * W) : 0;
    int base = py * W + px;
    // validity bitmasks over dy,dx in {-1,0,1}
    unsigned vmy = (py - 1 >= 0 ? 1u : 0u) | 2u | (py + 1 < H ? 4u : 0u);
    unsigned vmx = (px - 1 >= 0 ? 1u : 0u) | 2u | (px + 1 < W ? 4u : 0u);
    if (!inp) { vmy = 0; vmx = 0; }

    // incremental (ci, r) for the two k-rows: k = k0 + kl (+4); k0 starts 0
    int ci_a = 0, r_a = kl;
    int ci_b = 0, r_b = kl + 4;

    // A-load mapping
    int akk = t >> 6, acc_ = t & 63;

    float acc[4][4];
#pragma unroll
    for (int i = 0; i < 4; i++)
#pragma unroll
        for (int j = 0; j < 4; j++) acc[i][j] = 0.f;

    const float* wA = g_wT + akk * 256 + co0 + acc_;

    for (int k0 = 0; k0 < 2304; k0 += 8) {
        // ---- load A: wT[(k0+kk)][co0+cc], two rows per thread ----
        As[akk][acc_]     = __ldg(wA);
        As[akk + 4][acc_] = __ldg(wA + 4 * 256);
        wA += 8 * 256;

        // ---- load B: im2col rows kl and kl+4 ----
        {
            int dyI = r_a / 3;
            int dxI = r_a - dyI * 3;
            float v = 0.f;
            if (((vmy >> dyI) & 1u) && ((vmx >> dxI) & 1u))
                v = __ldg(&inb[ci_a * HW + base + (dyI - 1) * W + (dxI - 1)]);
            Bs[kl][pp] = v;
        }
        {
            int dyI = r_b / 3;
            int dxI = r_b - dyI * 3;
            float v = 0.f;
            if (((vmy >> dyI) & 1u) && ((vmx >> dxI) & 1u))
                v = __ldg(&inb[ci_b * HW + base + (dyI - 1) * W + (dxI - 1)]);
            Bs[kl + 4][pp] = v;
        }
        // advance k by 8: r += 8 (mod 9), carry to ci
        r_a += 8; if (r_a >= 9) { r_a -= 9; ci_a += 1; }
        r_b += 8; if (r_b >= 9) { r_b -= 9; ci_b += 1; }

        __syncthreads();
#pragma unroll
        for (int kk = 0; kk < 8; kk++) {
            float4 av = *(const float4*)(&As[kk][ty * 4]);
            float4 bv = *(const float4*)(&Bs[kk][tx * 4]);
            float aa[4] = {av.x, av.y, av.z, av.w};
            float bb[4] = {bv.x, bv.y, bv.z, bv.w};
#pragma unroll
            for (int i = 0; i < 4; i++)
#pragma unroll
                for (int j = 0; j < 4; j++)
                    acc[i][j] = fmaf(aa[i], bb[j], acc[i][j]);
        }
        __syncthreads();
    }

    // ---- epilogue: bias + ReLU, store to g_t (NCHW per level) ----
#pragma unroll
    for (int i = 0; i < 4; i++) {
        int co = co0 + ty * 4 + i;
        float bi = __ldg(&bias[co]);
        float* op = g_t + ((size_t)b * CHN + co) * Np;
#pragma unroll
        for (int j = 0; j < 4; j++) {
            int p = p0 + tx * 4 + j;
            if (p < Np) op[p] = fmaxf(acc[i][j] + bi, 0.f);
        }
    }
}

// ---------------------------------------------------------------------------
// 1x1 heads: 3 cls + 12 bbox outputs per pixel, K=256
// ---------------------------------------------------------------------------
__global__ void __launch_bounds__(128) head1x1(
    const float* __restrict__ cls_w, const float* __restrict__ cls_b,
    const float* __restrict__ bbox_w, const float* __restrict__ bbox_b,
    int Np, int noff)
{
    __shared__ float w[15][256];
    int b = blockIdx.y;
    int p = blockIdx.x * 128 + threadIdx.x;
    for (int i = threadIdx.x; i < 15 * 256; i += 128) {
        int o = i >> 8, c = i & 255;
        w[o][c] = (o < 3) ? cls_w[o * 256 + c] : bbox_w[(o - 3) * 256 + c];
    }
    __syncthreads();
    if (p >= Np) return;

    const float* tb = g_t + (size_t)b * CHN * Np + p;
    float acc[15];
#pragma unroll
    for (int o = 0; o < 15; o++) acc[o] = 0.f;
    for (int c = 0; c < 256; c++) {
        float v = tb[c * Np];
#pragma unroll
        for (int o = 0; o < 15; o++) acc[o] = fmaf(w[o][c], v, acc[o]);
    }
    int nb = b * NTOT + noff + p * 3;
#pragma unroll
    for (int a = 0; a < 3; a++) {
        g_logits[nb + a] = acc[a] + __ldg(&cls_b[a]);
#pragma unroll
        for (int j = 0; j < 4; j++)
            g_deltas[(size_t)(nb + a) * 4 + j] = acc[3 + a * 4 + j] + __ldg(&bbox_b[a * 4 + j]);
    }
}

// ---------------------------------------------------------------------------
// Radix top-k select per (batch, level). Unordered candidate set is safe:
// NMS is value-driven (ties measure-zero), all later gathers self-consistent.
// ---------------------------------------------------------------------------
__device__ __forceinline__ unsigned fkey(float f)
{
    unsigned u = __float_as_uint(f);
    return (u & 0x80000000u) ? ~u : (u | 0x80000000u);
}

__global__ void __launch_bounds__(512) topk_select()
{
    int blk = blockIdx.x;            // 0..7
    int b = blk >> 2, lvl = blk & 3;
    int N = c_Nanch[lvl], K = c_K[lvl];
    const float* lg = g_logits + b * NTOT + c_noff[lvl];

    __shared__ unsigned bins[256];
    __shared__ unsigned s_prefix, s_kk, s_cG, s_c1, s_c2;
    int t = threadIdx.x;
    if (t == 0) { s_prefix = 0u; s_kk = (unsigned)K; }
    __syncthreads();

    for (int pass = 3; pass >= 0; pass--) {
        int sh = pass * 8;
        if (t < 256) bins[t] = 0u;
        __syncthreads();
        unsigned prefix = s_prefix;
        unsigned hmask = (pass == 3) ? 0u : (0xFFFFFFFFu << (sh + 8));
        for (int i = t; i < N; i += 512) {
            unsigned key = fkey(lg[i]);
            if ((key & hmask) == prefix)
                atomicAdd(&bins[(key >> sh) & 255u], 1u);
        }
        __syncthreads();
        if (t == 0) {
            unsigned kk = s_kk, cum = 0u;
            int v = 255;
            for (; v > 0; v--) {
                if (cum + bins[v] >= kk) break;
                cum += bins[v];
            }
            s_kk = kk - cum;
            s_prefix = prefix | ((unsigned)v << sh);
        }
        __syncthreads();
    }
    unsigned T = s_prefix;
    if (t == 0) { s_cG = 0u; s_c1 = 0u; s_c2 = 0u; }
    __syncthreads();

    unsigned lc = 0u;
    for (int i = t; i < N; i += 512)
        if (fkey(lg[i]) > T) lc++;
    if (lc) atomicAdd(&s_cG, lc);
    __syncthreads();
    unsigned TG = s_cG;

    int* outn = g_cand_n + b * TOTC + c_cbase[lvl];
    for (int i = t; i < N; i += 512) {
        unsigned key = fkey(lg[i]);
        if (key > T) {
            unsigned s = atomicAdd(&s_c1, 1u);
            outn[s] = i;
        } else if (key == T) {
            unsigned s = TG + atomicAdd(&s_c2, 1u);
            if (s < (unsigned)K) outn[s] = i;
        }
    }
}

// ---------------------------------------------------------------------------
// Decode candidates: anchors -> boxes, clip, min-size/score filter
// ---------------------------------------------------------------------------
__global__ void __launch_bounds__(256) decode_cand()
{
    int tid = blockIdx.x * 256 + threadIdx.x;
    if (tid >= BATCH * TOTC) return;
    int b = tid / TOTC, c = tid - b * TOTC;
    int lvl = c / 1000; if (lvl > 3) lvl = 3;
    int n = g_cand_n[tid];
    int W = c_W[lvl];
    float stride = c_stride[lvl], size = c_size[lvl];

    int a = n % 3, cell = n / 3;
    int gx = cell % W, gy = cell / W;

    float ratio = (a == 0) ? 0.5f : ((a == 1) ? 1.0f : 2.0f);
    float hr = sqrtf(ratio);
    float wr = 1.0f / hr;
    float ws = wr * size, hs = hr * size;
    float w2 = rintf(ws * 0.5f);
    float h2 = rintf(hs * 0.5f);
    float sx = gx * stride, sy = gy * stride;
    float x1 = sx - w2, y1 = sy - h2, x2 = sx + w2, y2 = sy + h2;

    float wa = x2 - x1, ha = y2 - y1;
    float cxa = x1 + 0.5f * wa, cya = y1 + 0.5f * ha;

    int gi = b * NTOT + c_noff[lvl] + n;
    float score = g_logits[gi];
    const float* d = g_deltas + (size_t)gi * 4;
    float dx = d[0], dy = d[1];
    float dw = fminf(d[2], CLAMPF), dh = fminf(d[3], CLAMPF);
    float cx = dx * wa + cxa, cy = dy * ha + cya;
    float bw = expf(dw) * wa, bh = expf(dh) * ha;
    float bx1 = cx - 0.5f * bw, by1 = cy - 0.5f * bh;
    float bx2 = cx + 0.5f * bw, by2 = cy + 0.5f * bh;
    bx1 = fminf(fmaxf(bx1, 0.f), IMG);
    by1 = fminf(fmaxf(by1, 0.f), IMG);
    bx2 = fminf(fmaxf(bx2, 0.f), IMG);
    by2 = fminf(fmaxf(by2, 0.f), IMG);

    float bws = bx2 - bx1, bhs = by2 - by1;
    bool bad = (bws < 0.001f) || (bhs < 0.001f) || (score < 0.0f);
    g_sc[tid] = bad ? NEGF : score;

    float off = (float)lvl * 4096.0f;
    float* bp = g_box + (size_t)tid * 4;
    bp[0] = bx1; bp[1] = by1; bp[2] = bx2; bp[3] = by2;
    float* op = g_obox + (size_t)tid * 4;
    op[0] = bx1 + off; op[1] = by1 + off; op[2] = bx2 + off; op[3] = by2 + off;
}

// ---------------------------------------------------------------------------
// Greedy NMS, one block per batch. All candidate state in registers.
// ---------------------------------------------------------------------------
#define NMSTH 512
#define NMSLP 7     // 512*7 = 3584 >= 3507

__global__ void __launch_bounds__(NMSTH) nms_kernel()
{
    int b = blockIdx.x;
    int t = threadIdx.x;

    float sc[NMSLP], ax[NMSLP], ay[NMSLP], bx2[NMSLP], by2[NMSLP], ar[NMSLP];
    int gidx[NMSLP];
#pragma unroll
    for (int l = 0; l < NMSLP; l++) {
        int i = t + l * NMSTH;
        gidx[l] = i;
        if (i < TOTC) {
            sc[l] = g_sc[b * TOTC + i];
            const float* bb = g_obox + (size_t)(b * TOTC + i) * 4;
            ax[l] = bb[0]; ay[l] = bb[1]; bx2[l] = bb[2]; by2[l] = bb[3];
            ar[l] = (bx2[l] - ax[l]) * (by2[l] - ay[l]);
        } else {
            sc[l] = -INFINITY; ax[l] = ay[l] = bx2[l] = by2[l] = 0.f; ar[l] = 0.f;
        }
    }

    __shared__ float rv[16];
    __shared__ int   ri[16];
    __shared__ float bb[6];   // x1,y1,x2,y2,area,score of winner

    for (int it = 0; it < POST; it++) {
        // local argmax (lowest-index tie-break)
        float best = -INFINITY; int bi = 0x7fffffff;
#pragma unroll
        for (int l = 0; l < NMSLP; l++)
            if (sc[l] > best || (sc[l] == best && gidx[l] < bi)) { best = sc[l]; bi = gidx[l]; }
        // warp reduce
#pragma unroll
        for (int o = 16; o; o >>= 1) {
            float ov = __shfl_down_sync(0xFFFFFFFFu, best, o);
            int   oi = __shfl_down_sync(0xFFFFFFFFu, bi, o);
            if (ov > best || (ov == best && oi < bi)) { best = ov; bi = oi; }
        }
        if ((t & 31) == 0) { rv[t >> 5] = best; ri[t >> 5] = bi; }
        __syncthreads();
        if (t < 32) {
            float v2 = (t < 16) ? rv[t] : -INFINITY;
            int   i2 = (t < 16) ? ri[t] : 0x7fffffff;
#pragma unroll
            for (int o = 8; o; o >>= 1) {
                float ov = __shfl_down_sync(0xFFFFFFFFu, v2, o);
                int   oi = __shfl_down_sync(0xFFFFFFFFu, i2, o);
                if (ov > v2 || (ov == v2 && oi < i2)) { v2 = ov; i2 = oi; }
            }
            if (t == 0) { ri[0] = i2; }
        }
        __syncthreads();
        int j = ri[0];

        // winner's owner publishes its box/area/score and kills its score
        int lo = j - t;
        if (lo >= 0 && (lo % NMSTH) == 0 && (lo / NMSTH) < NMSLP) {
            int l = lo / NMSTH;
            bb[0] = ax[l]; bb[1] = ay[l]; bb[2] = bx2[l]; bb[3] = by2[l];
            bb[4] = ar[l]; bb[5] = sc[l];
            sc[l] = NEGF;
        }
        __syncthreads();

        float jx1 = bb[0], jy1 = bb[1], jx2 = bb[2], jy2 = bb[3], ja = bb[4];
        bool ok = bb[5] > NEGF * 0.5f;
        if (t == 0) {
            float* rr = g_rois + (size_t)(b * POST + it) * 4;
            if (ok) {
                const float* cb = g_box + (size_t)(b * TOTC + j) * 4;
                rr[0] = cb[0]; rr[1] = cb[1]; rr[2] = cb[2]; rr[3] = cb[3];
            } else {
                rr[0] = 0.f; rr[1] = 0.f; rr[2] = 0.f; rr[3] = 0.f;
            }
        }
        // suppression
#pragma unroll
        for (int l = 0; l < NMSLP; l++) {
            float xx1 = fmaxf(jx1, ax[l]),  yy1 = fmaxf(jy1, ay[l]);
            float xx2 = fminf(jx2, bx2[l]), yy2 = fminf(jy2, by2[l]);
            float inter = fmaxf(xx2 - xx1, 0.f) * fmaxf(yy2 - yy1, 0.f);
            float iou = inter / fmaxf(ja + ar[l] - inter, 1e-9f);
            if (iou > 0.7f) sc[l] = NEGF;
        }
        __syncthreads();
    }
}

// ---------------------------------------------------------------------------
// ROI align on feat3 (13x13, channels-last), 7x7 out, sampling 2
// One block per ROI, one thread per channel.
// ---------------------------------------------------------------------------
__global__ void __launch_bounds__(256) roi_align_kernel()
{
    int roi = blockIdx.x;          // 0..599
    int b = roi / POST;
    int c = threadIdx.x;

    const float* R = g_rois + (size_t)roi * 4;
    const float scale = 0.015625f;  // 13/832
    float x1 = R[0] * scale - 0.5f, y1 = R[1] * scale - 0.5f;
    float x2 = R[2] * scale - 0.5f, y2 = R[3] * scale - 0.5f;

    float acc[49];
#pragma unroll
    for (int i = 0; i < 49; i++) acc[i] = 0.f;

    const float* F = g_ft3 + (size_t)b * 169 * 256 + c;

#pragma unroll
    for (int py = 0; py < 14; py++) {
        float gy = ((float)py + 0.5f) / 14.0f;
        float yy = y1 + gy * (y2 - y1);
        bool vy = (yy >= -1.0f) && (yy <= 13.0f);
        float y = fminf(fmaxf(yy, 0.f), 12.f);
        int y0 = (int)floorf(y);
        int y1i = min(y0 + 1, 12);
        float ly = y - (float)y0;
#pragma unroll
        for (int px = 0; px < 14; px++) {
            float gx = ((float)px + 0.5f) / 14.0f;
            float xx = x1 + gx * (x2 - x1);
            bool vx = (xx >= -1.0f) && (xx <= 13.0f);
            float x = fminf(fmaxf(xx, 0.f), 12.f);
            int x0 = (int)floorf(x);
            int x1i = min(x0 + 1, 12);
            float lx = x - (float)x0;

            float c00 = __ldg(&F[(y0 * 13 + x0) * 256]);
            float c01 = __ldg(&F[(y0 * 13 + x1i) * 256]);
            float c10 = __ldg(&F[(y1i * 13 + x0) * 256]);
            float c11 = __ldg(&F[(y1i * 13 + x1i) * 256]);
            float v = c00 * (1.f - ly) * (1.f - lx) + c01 * (1.f - ly) * lx
                    + c10 * ly * (1.f - lx)        + c11 * ly * lx;
            if (!(vy && vx)) v = 0.f;
            acc[(py >> 1) * 7 + (px >> 1)] += v;
        }
    }

    float* out = g_rf + (size_t)roi * 12544 + c * 49;
#pragma unroll
    for (int i = 0; i < 49; i++) out[i] = acc[i] * 0.25f;
}

// ---------------------------------------------------------------------------
// FC: out[600][1408] = rf[600][12544] @ fc_w[1408][12544]^T + fc_b
// 64x64x8 tiles, 4x4 micro-tile.
// ---------------------------------------------------------------------------
__global__ void __launch_bounds__(256) fc_gemm(
    const float* __restrict__ fw, const float* __restrict__ fb,
    float* __restrict__ out)
{
    __shared__ __align__(16) float As[8][68];
    __shared__ __align__(16) float Bs[8][68];

    int n0 = blockIdx.x * 64;
    int m0 = blockIdx.y * 64;
    int t = threadIdx.x;
    int tx = t & 15, ty = t >> 4;
    int lr = t >> 2, lk = (t & 3) * 2;

    float acc[4][4];
#pragma unroll
    for (int i = 0; i < 4; i++)
#pragma unroll
        for (int j = 0; j < 4; j++) acc[i][j] = 0.f;

    bool mval = (m0 + lr) < 600;
    const float* ap = g_rf + (size_t)(m0 + lr) * 12544 + lk;
    const float* bp = fw + (size_t)(n0 + lr) * 12544 + lk;

    for (int k0 = 0; k0 < 12544; k0 += 8) {
        float a0 = 0.f, a1 = 0.f;
        if (mval) { a0 = __ldg(ap); a1 = __ldg(ap + 1); }
        As[lk][lr] = a0; As[lk + 1][lr] = a1;
        Bs[lk][lr] = __ldg(bp); Bs[lk + 1][lr] = __ldg(bp + 1);
        ap += 8; bp += 8;
        __syncthreads();
#pragma unroll
        for (int kk = 0; kk < 8; kk++) {
            float4 av = *(const float4*)(&As[kk][ty * 4]);
            float4 bv = *(const float4*)(&Bs[kk][tx * 4]);
            float aa[4] = {av.x, av.y, av.z, av.w};
            float bbv[4] = {bv.x, bv.y, bv.z, bv.w};
#pragma unroll
            for (int i = 0; i < 4; i++)
#pragma unroll
                for (int j = 0; j < 4; j++)
                    acc[i][j] = fmaf(aa[i], bbv[j], acc[i][j]);
        }
        __syncthreads();
    }

#pragma unroll
    for (int i = 0; i < 4; i++) {
        int m = m0 + ty * 4 + i;
        if (m >= 600) continue;
#pragma unroll
        for (int j = 0; j < 4; j++) {
            int n = n0 + tx * 4 + j;
            out[(size_t)m * 1408 + n] = acc[i][j] + __ldg(&fb[n]);
        }
    }
}

// ---------------------------------------------------------------------------
// Launch
// ---------------------------------------------------------------------------
extern "C" void kernel_launch(void* const* d_in, const int* in_sizes, int n_in,
                              void* d_out, int out_size)
{
    const float* feat[4] = {(const float*)d_in[0], (const float*)d_in[1],
                            (const float*)d_in[2], (const float*)d_in[3]};
    const float* conv_w = (const float*)d_in[4];
    const float* conv_b = (const float*)d_in[5];
    const float* cls_w  = (const float*)d_in[6];
    const float* cls_b  = (const float*)d_in[7];
    const float* bbox_w = (const float*)d_in[8];
    const float* bbox_b = (const float*)d_in[9];
    const float* fc_w   = (const float*)d_in[10];
    const float* fc_b   = (const float*)d_in[11];

    prep_wT<<<2304, 256>>>(conv_w);
    prep_ft3<<<(BATCH * 169 * 256 + 255) / 256, 256>>>(feat[3]);

    const int Ws[4]    = {104, 52, 26, 13};
    const int noffs[4] = {0, 32448, 40560, 42588};
    for (int l = 0; l < 4; l++) {
        int W = Ws[l], H = W, Np = W * W;
        dim3 gc((Np + 63) / 64, 4, BATCH);
        conv3x3_gemm<<<gc, 256>>>(feat[l], conv_b, H, W, Np);
        dim3 gh((Np + 127) / 128, BATCH);
        head1x1<<<gh, 128>>>(cls_w, cls_b, bbox_w, bbox_b, Np, noffs[l]);
    }

    topk_select<<<8, 512>>>();
    decode_cand<<<(BATCH * TOTC + 255) / 256, 256>>>();
    nms_kernel<<<BATCH, NMSTH>>>();
    roi_align_kernel<<<BATCH * POST, 256>>>();
    fc_gemm<<<dim3(1408 / 64, (600 + 63) / 64), 256>>>(fc_w, fc_b, (float*)d_out);
}

// round 4
// speedup vs baseline: 1.0198x; 1.0198x over previous
#include <cuda_runtime.h>
#include <math.h>

// ---------------------------------------------------------------------------
// Fixed problem shapes
// ---------------------------------------------------------------------------
#define BATCH 2
#define CHN   256
#define NTOT  43095          // anchors per batch across 4 levels
#define TOTC  3507           // top-k candidates per batch (1000+1000+1000+507)
#define POST  300
#define NEGF  (-1e30f)
#define CLAMPF 4.135166556742356f   // log(1000/16)
#define IMG   832.0f

__device__ __constant__ int   c_W[4]      = {104, 52, 26, 13};
__device__ __constant__ int   c_Nanch[4]  = {32448, 8112, 2028, 507};
__device__ __constant__ int   c_noff[4]   = {0, 32448, 40560, 42588};
__device__ __constant__ int   c_K[4]      = {1000, 1000, 1000, 507};
__device__ __constant__ int   c_cbase[4]  = {0, 1000, 2000, 3000};
__device__ __constant__ float c_stride[4] = {8.f, 16.f, 32.f, 64.f};
__device__ __constant__ float c_size[4]   = {32.f, 64.f, 128.f, 256.f};

// ---------------------------------------------------------------------------
// Static device scratch
// ---------------------------------------------------------------------------
__device__ __align__(16) float g_t[BATCH * CHN * 10816];   // conv+relu out (per level)
__device__ __align__(16) float g_wT[2304 * CHN];           // conv w, [tap*256+ci][co]
__device__ __align__(16) float g_ft3[BATCH * 169 * CHN];   // feat3 channels-last
__device__ float g_logits[BATCH * NTOT];
__device__ float g_deltas[BATCH * NTOT * 4];
__device__ int   g_cand_n[BATCH * TOTC];
__device__ float g_sc[BATCH * TOTC];
__device__ float g_box[BATCH * TOTC * 4];
__device__ float g_obox[BATCH * TOTC * 4];
__device__ float g_rois[BATCH * POST * 4];
__device__ __align__(16) float g_rf[600 * 12544];          // ROI features (FC input)
__device__ __align__(16) float g_fcpart[2 * 600 * 1408];   // split-K partials

// ---------------------------------------------------------------------------
// Prep: conv weights -> [k' = tap*256 + ci][co];   feat3 -> channels-last
// ---------------------------------------------------------------------------
__global__ void prep_wT(const float* __restrict__ cw)
{
    int kp = blockIdx.x;        // 0..2303 : kp = r*256 + ci
    int co = threadIdx.x;       // 0..255
    int r  = kp >> 8;
    int ci = kp & 255;
    g_wT[kp * 256 + co] = cw[co * 2304 + ci * 9 + r];
}

__global__ void prep_ft3(const float* __restrict__ f3)
{
    int idx = blockIdx.x * 256 + threadIdx.x;
    if (idx >= BATCH * 169 * 256) return;
    int c = idx & 255;
    int p = (idx >> 8) % 169;
    int b = idx / (169 * 256);
    g_ft3[idx] = f3[(b * 256 + c) * 169 + p];
}

// ---------------------------------------------------------------------------
// Conv 3x3 (+bias,+ReLU) as implicit GEMM, K reordered as k' = tap*256 + ci.
// Tile 64(co) x 128(px), 256 threads, 4x8 micro, BK=16, double-buffered.
// Each 16-k chunk has ONE tap -> one predicate + strided loads.
// ---------------------------------------------------------------------------
#define CONV_LOAD(k0) do {                                                      \
    const float4 wv = *(const float4*)(g_wT + (size_t)((k0) + a_k) * 256 + co0 + a_c); \
    astg[0] = wv.x; astg[1] = wv.y; astg[2] = wv.z; astg[3] = wv.w;             \
    int r_ = (k0) >> 8;                                                         \
    int dy_ = r_ / 3, dx_ = r_ - dy_ * 3;                                       \
    bool vld_ = ((vmy >> dy_) & 1u) && ((vmx >> dx_) & 1u);                     \
    const float* bptr_ = inb + (size_t)(((k0) & 255) + kh) * HW + base          \
                             + (dy_ - 1) * W + (dx_ - 1);                       \
    _Pragma("unroll")                                                           \
    for (int i_ = 0; i_ < 8; i_++)                                              \
        bstg[i_] = vld_ ? __ldg(bptr_ + (size_t)i_ * 2 * HW) : 0.f;             \
} while (0)

#define CONV_STORE(bf) do {                                                     \
    *(float4*)&As[bf][a_k][a_c] = make_float4(astg[0], astg[1], astg[2], astg[3]); \
    _Pragma("unroll")                                                           \
    for (int i_ = 0; i_ < 8; i_++) Bs[bf][kh + 2 * i_][pp] = bstg[i_];          \
} while (0)

#define CONV_COMPUTE(bf) do {                                                   \
    _Pragma("unroll")                                                           \
    for (int kk = 0; kk < 16; kk++) {                                           \
        float4 av = *(const float4*)&As[bf][kk][ty4];                           \
        float4 b0 = *(const float4*)&Bs[bf][kk][tx8];                           \
        float4 b1 = *(const float4*)&Bs[bf][kk][tx8 + 4];                       \
        float aa[4] = {av.x, av.y, av.z, av.w};                                 \
        float bbv[8] = {b0.x, b0.y, b0.z, b0.w, b1.x, b1.y, b1.z, b1.w};        \
        _Pragma("unroll")                                                       \
        for (int i2 = 0; i2 < 4; i2++)                                          \
            _Pragma("unroll")                                                   \
            for (int j2 = 0; j2 < 8; j2++)                                      \
                acc[i2][j2] = fmaf(aa[i2], bbv[j2], acc[i2][j2]);               \
    }                                                                           \
} while (0)

__global__ void __launch_bounds__(256) conv3x3_gemm(
    const float* __restrict__ in, const float* __restrict__ bias,
    int H, int W, int Np)
{
    __shared__ __align__(16) float As[2][16][64];
    __shared__ __align__(16) float Bs[2][16][128];

    int b   = blockIdx.z;
    int co0 = blockIdx.y * 64;
    int p0  = blockIdx.x * 128;
    int t   = threadIdx.x;

    const float* inb = in + (size_t)b * CHN * H * W;
    int HW = H * W;

    // B gather mapping: pixel pp, k-half kh (rows kh, kh+2, ..., kh+14)
    int pp = t & 127;
    int kh = t >> 7;
    int pix = p0 + pp;
    bool inp = pix < Np;
    int py = inp ? (pix / W) : 0;
    int px = inp ? (pix - py * W) : 0;
    int base = py * W + px;
    unsigned vmy = ((py > 0) ? 1u : 0u) | 2u | ((py + 1 < H) ? 4u : 0u);
    unsigned vmx = ((px > 0) ? 1u : 0u) | 2u | ((px + 1 < W) ? 4u : 0u);
    if (!inp) vmy = 0u;

    // A load mapping
    int a_k = t >> 4;
    int a_c = (t & 15) * 4;
    // compute mapping
    int tx8 = (t & 15) * 8;
    int ty4 = (t >> 4) * 4;

    float acc[4][8];
#pragma unroll
    for (int i = 0; i < 4; i++)
#pragma unroll
        for (int j = 0; j < 8; j++) acc[i][j] = 0.f;

    float astg[4], bstg[8];

    CONV_LOAD(0);
    CONV_STORE(0);
    __syncthreads();

    int buf = 0;
    for (int k0 = 16; k0 < 2304; k0 += 16) {
        CONV_LOAD(k0);
        CONV_COMPUTE(buf);
        CONV_STORE(buf ^ 1);
        __syncthreads();
        buf ^= 1;
    }
    CONV_COMPUTE(buf);

    // epilogue
#pragma unroll
    for (int i = 0; i < 4; i++) {
        int co = co0 + (ty4 >> 2) * 4 + i;   // co0 + ty*4 + i
        float bi = __ldg(&bias[co]);
        float* op = g_t + ((size_t)b * CHN + co) * Np;
#pragma unroll
        for (int j = 0; j < 8; j++) {
            int p = p0 + tx8 + j;
            if (p < Np) op[p] = fmaxf(acc[i][j] + bi, 0.f);
        }
    }
}

// ---------------------------------------------------------------------------
// 1x1 heads: 64 pixels/block, 4 channel-quarters across warps, smem reduce.
// ---------------------------------------------------------------------------
__global__ void __launch_bounds__(256) head1x1(
    const float* __restrict__ cls_w, const float* __restrict__ cls_b,
    const float* __restrict__ bbox_w, const float* __restrict__ bbox_b,
    int Np, int noff)
{
    __shared__ float w[15][256];
    __shared__ float red[4][15][65];
    int b = blockIdx.y;
    int t = threadIdx.x;
    for (int i = t; i < 15 * 256; i += 256) {
        int o = i >> 8, c = i & 255;
        w[o][c] = (o < 3) ? cls_w[o * 256 + c] : bbox_w[(o - 3) * 256 + c];
    }
    __syncthreads();

    int pl = t & 63, cq = t >> 6;
    int p = blockIdx.x * 64 + pl;
    float acc[15];
#pragma unroll
    for (int o = 0; o < 15; o++) acc[o] = 0.f;

    if (p < Np) {
        const float* tb = g_t + ((size_t)b * CHN + cq * 64) * Np + p;
#pragma unroll 4
        for (int c = 0; c < 64; c++) {
            float v = __ldg(tb + (size_t)c * Np);
#pragma unroll
            for (int o = 0; o < 15; o++) acc[o] = fmaf(w[o][cq * 64 + c], v, acc[o]);
        }
    }
#pragma unroll
    for (int o = 0; o < 15; o++) red[cq][o][pl] = acc[o];
    __syncthreads();

    for (int idx = t; idx < 64 * 15; idx += 256) {
        int pl2 = idx & 63, o = idx >> 6;
        int p2 = blockIdx.x * 64 + pl2;
        if (p2 >= Np) continue;
        float s = red[0][o][pl2] + red[1][o][pl2] + red[2][o][pl2] + red[3][o][pl2];
        int nb = b * NTOT + noff + p2 * 3;
        if (o < 3) {
            g_logits[nb + o] = s + __ldg(&cls_b[o]);
        } else {
            int oo = o - 3;
            int a = oo >> 2, j = oo & 3;
            g_deltas[(size_t)(nb + a) * 4 + j] = s + __ldg(&bbox_b[oo]);
        }
    }
}

// ---------------------------------------------------------------------------
// Radix top-k select per (batch, level). Unordered set is safe (NMS is
// value-driven; gathers self-consistent).
// ---------------------------------------------------------------------------
__device__ __forceinline__ unsigned fkey(float f)
{
    unsigned u = __float_as_uint(f);
    return (u & 0x80000000u) ? ~u : (u | 0x80000000u);
}

__global__ void __launch_bounds__(512) topk_select()
{
    int blk = blockIdx.x;
    int b = blk >> 2, lvl = blk & 3;
    int N = c_Nanch[lvl], K = c_K[lvl];
    const float* lg = g_logits + b * NTOT + c_noff[lvl];

    __shared__ unsigned bins[256];
    __shared__ unsigned s_prefix, s_kk, s_cG, s_c1, s_c2;
    int t = threadIdx.x;
    if (t == 0) { s_prefix = 0u; s_kk = (unsigned)K; }
    __syncthreads();

    for (int pass = 3; pass >= 0; pass--) {
        int sh = pass * 8;
        if (t < 256) bins[t] = 0u;
        __syncthreads();
        unsigned prefix = s_prefix;
        unsigned hmask = (pass == 3) ? 0u : (0xFFFFFFFFu << (sh + 8));
        for (int i = t; i < N; i += 512) {
            unsigned key = fkey(lg[i]);
            if ((key & hmask) == prefix)
                atomicAdd(&bins[(key >> sh) & 255u], 1u);
        }
        __syncthreads();
        if (t == 0) {
            unsigned kk = s_kk, cum = 0u;
            int v = 255;
            for (; v > 0; v--) {
                if (cum + bins[v] >= kk) break;
                cum += bins[v];
            }
            s_kk = kk - cum;
            s_prefix = prefix | ((unsigned)v << sh);
        }
        __syncthreads();
    }
    unsigned T = s_prefix;
    if (t == 0) { s_cG = 0u; s_c1 = 0u; s_c2 = 0u; }
    __syncthreads();

    unsigned lc = 0u;
    for (int i = t; i < N; i += 512)
        if (fkey(lg[i]) > T) lc++;
    if (lc) atomicAdd(&s_cG, lc);
    __syncthreads();
    unsigned TG = s_cG;

    int* outn = g_cand_n + b * TOTC + c_cbase[lvl];
    for (int i = t; i < N; i += 512) {
        unsigned key = fkey(lg[i]);
        if (key > T) {
            unsigned s = atomicAdd(&s_c1, 1u);
            outn[s] = i;
        } else if (key == T) {
            unsigned s = TG + atomicAdd(&s_c2, 1u);
            if (s < (unsigned)K) outn[s] = i;
        }
    }
}

// ---------------------------------------------------------------------------
// Decode candidates
// ---------------------------------------------------------------------------
__global__ void __launch_bounds__(256) decode_cand()
{
    int tid = blockIdx.x * 256 + threadIdx.x;
    if (tid >= BATCH * TOTC) return;
    int b = tid / TOTC, c = tid - b * TOTC;
    int lvl = c / 1000; if (lvl > 3) lvl = 3;
    int n = g_cand_n[tid];
    int W = c_W[lvl];
    float stride = c_stride[lvl], size = c_size[lvl];

    int a = n % 3, cell = n / 3;
    int gx = cell % W, gy = cell / W;

    float ratio = (a == 0) ? 0.5f : ((a == 1) ? 1.0f : 2.0f);
    float hr = sqrtf(ratio);
    float wr = 1.0f / hr;
    float ws = wr * size, hs = hr * size;
    float w2 = rintf(ws * 0.5f);
    float h2 = rintf(hs * 0.5f);
    float sx = gx * stride, sy = gy * stride;
    float x1 = sx - w2, y1 = sy - h2, x2 = sx + w2, y2 = sy + h2;

    float wa = x2 - x1, ha = y2 - y1;
    float cxa = x1 + 0.5f * wa, cya = y1 + 0.5f * ha;

    int gi = b * NTOT + c_noff[lvl] + n;
    float score = g_logits[gi];
    const float* d = g_deltas + (size_t)gi * 4;
    float dx = d[0], dy = d[1];
    float dw = fminf(d[2], CLAMPF), dh = fminf(d[3], CLAMPF);
    float cx = dx * wa + cxa, cy = dy * ha + cya;
    float bw = expf(dw) * wa, bh = expf(dh) * ha;
    float bx1 = cx - 0.5f * bw, by1 = cy - 0.5f * bh;
    float bx2 = cx + 0.5f * bw, by2 = cy + 0.5f * bh;
    bx1 = fminf(fmaxf(bx1, 0.f), IMG);
    by1 = fminf(fmaxf(by1, 0.f), IMG);
    bx2 = fminf(fmaxf(bx2, 0.f), IMG);
    by2 = fminf(fmaxf(by2, 0.f), IMG);

    float bws = bx2 - bx1, bhs = by2 - by1;
    bool bad = (bws < 0.001f) || (bhs < 0.001f) || (score < 0.0f);
    g_sc[tid] = bad ? NEGF : score;

    float off = (float)lvl * 4096.0f;
    float* bp = g_box + (size_t)tid * 4;
    bp[0] = bx1; bp[1] = by1; bp[2] = bx2; bp[3] = by2;
    float* op = g_obox + (size_t)tid * 4;
    op[0] = bx1 + off; op[1] = by1 + off; op[2] = bx2 + off; op[3] = by2 + off;
}

// ---------------------------------------------------------------------------
// Greedy NMS: packed 64-bit (score,~idx) key, warp reduce + shared atomicMax,
// double-buffered best slot -> 2 syncs/iter.
// ---------------------------------------------------------------------------
#define NMSTH 512
#define NMSLP 7

__global__ void __launch_bounds__(NMSTH) nms_kernel()
{
    int b = blockIdx.x;
    int t = threadIdx.x;

    float sc[NMSLP], ax[NMSLP], ay[NMSLP], bx2[NMSLP], by2[NMSLP], ar[NMSLP];
#pragma unroll
    for (int l = 0; l < NMSLP; l++) {
        int i = t + l * NMSTH;
        if (i < TOTC) {
            sc[l] = g_sc[b * TOTC + i];
            const float* bbp = g_obox + (size_t)(b * TOTC + i) * 4;
            ax[l] = bbp[0]; ay[l] = bbp[1]; bx2[l] = bbp[2]; by2[l] = bbp[3];
            ar[l] = (bx2[l] - ax[l]) * (by2[l] - ay[l]);
        } else {
            sc[l] = -INFINITY; ax[l] = ay[l] = bx2[l] = by2[l] = 0.f; ar[l] = 0.f;
        }
    }

    __shared__ unsigned long long s_best[2];
    __shared__ float bb[6];
    if (t == 0) { s_best[0] = 0ull; s_best[1] = 0ull; }
    __syncthreads();

    for (int it = 0; it < POST; it++) {
        unsigned long long key = 0ull;
#pragma unroll
        for (int l = 0; l < NMSLP; l++) {
            unsigned idx = (unsigned)(t + l * NMSTH);
            unsigned long long kl2 = ((unsigned long long)fkey(sc[l]) << 32)
                                   | (unsigned long long)(0x7FFFFFFFu - idx);
            if (kl2 > key) key = kl2;
        }
#pragma unroll
        for (int o = 16; o; o >>= 1) {
            unsigned long long ok2 = __shfl_down_sync(0xFFFFFFFFu, key, o);
            if (ok2 > key) key = ok2;
        }
        if ((t & 31) == 0) atomicMax(&s_best[it & 1], key);
        __syncthreads();

        unsigned long long bk = s_best[it & 1];
        int j = (int)(0x7FFFFFFFu - (unsigned)(bk & 0xFFFFFFFFull));

        int lo = j - t;
        if (lo >= 0 && (lo & (NMSTH - 1)) == 0) {
            int l = lo >> 9;                 // NMSTH = 512
            if (l < NMSLP) {
                bb[0] = ax[l]; bb[1] = ay[l]; bb[2] = bx2[l]; bb[3] = by2[l];
                bb[4] = ar[l]; bb[5] = sc[l];
                sc[l] = NEGF;
            }
        }
        if (t == 0) s_best[(it + 1) & 1] = 0ull;
        __syncthreads();

        float jx1 = bb[0], jy1 = bb[1], jx2 = bb[2], jy2 = bb[3], ja = bb[4];
        bool ok = bb[5] > NEGF * 0.5f;
        if (t == 0) {
            float* rr = g_rois + (size_t)(b * POST + it) * 4;
            if (ok) {
                const float* cb = g_box + (size_t)(b * TOTC + j) * 4;
                rr[0] = cb[0]; rr[1] = cb[1]; rr[2] = cb[2]; rr[3] = cb[3];
            } else {
                rr[0] = 0.f; rr[1] = 0.f; rr[2] = 0.f; rr[3] = 0.f;
            }
        }
#pragma unroll
        for (int l = 0; l < NMSLP; l++) {
            float xx1 = fmaxf(jx1, ax[l]),  yy1 = fmaxf(jy1, ay[l]);
            float xx2 = fminf(jx2, bx2[l]), yy2 = fminf(jy2, by2[l]);
            float inter = fmaxf(xx2 - xx1, 0.f) * fmaxf(yy2 - yy1, 0.f);
            float iou = inter / fmaxf(ja + ar[l] - inter, 1e-9f);
            if (iou > 0.7f) sc[l] = NEGF;
        }
        // no sync needed here: next iter's first sync protects bb/s_best
    }
}

// ---------------------------------------------------------------------------
// ROI align on feat3 (13x13 channels-last), 7x7 out, sampling 2.
// ---------------------------------------------------------------------------
__global__ void __launch_bounds__(256) roi_align_kernel()
{
    int roi = blockIdx.x;
    int b = roi / POST;
    int c = threadIdx.x;

    const float* R = g_rois + (size_t)roi * 4;
    const float scale = 0.015625f;   // 13/832
    float x1 = R[0] * scale - 0.5f, y1 = R[1] * scale - 0.5f;
    float x2 = R[2] * scale - 0.5f, y2 = R[3] * scale - 0.5f;

    float acc[49];
#pragma unroll
    for (int i = 0; i < 49; i++) acc[i] = 0.f;

    const float* F = g_ft3 + (size_t)b * 169 * 256 + c;

#pragma unroll
    for (int py = 0; py < 14; py++) {
        float gy = ((float)py + 0.5f) / 14.0f;
        float yy = y1 + gy * (y2 - y1);
        bool vy = (yy >= -1.0f) && (yy <= 13.0f);
        float y = fminf(fmaxf(yy, 0.f), 12.f);
        int y0 = (int)floorf(y);
        int y1i = min(y0 + 1, 12);
        float ly = y - (float)y0;
#pragma unroll
        for (int px = 0; px < 14; px++) {
            float gx = ((float)px + 0.5f) / 14.0f;
            float xx = x1 + gx * (x2 - x1);
            bool vx = (xx >= -1.0f) && (xx <= 13.0f);
            float x = fminf(fmaxf(xx, 0.f), 12.f);
            int x0 = (int)floorf(x);
            int x1i = min(x0 + 1, 12);
            float lx = x - (float)x0;

            float c00 = __ldg(&F[(y0 * 13 + x0) * 256]);
            float c01 = __ldg(&F[(y0 * 13 + x1i) * 256]);
            float c10 = __ldg(&F[(y1i * 13 + x0) * 256]);
            float c11 = __ldg(&F[(y1i * 13 + x1i) * 256]);
            float v = c00 * (1.f - ly) * (1.f - lx) + c01 * (1.f - ly) * lx
                    + c10 * ly * (1.f - lx)        + c11 * ly * lx;
            if (!(vy && vx)) v = 0.f;
            acc[(py >> 1) * 7 + (px >> 1)] += v;
        }
    }

    float* out = g_rf + (size_t)roi * 12544 + c * 49;
#pragma unroll
    for (int i = 0; i < 49; i++) out[i] = acc[i] * 0.25f;
}

// ---------------------------------------------------------------------------
// FC split-K GEMM: part[kidx][600][1408] = rf[:, Khalf] @ fw[:, Khalf]^T
// Tile 64(m) x 128(n), BK=16, double-buffered, blockIdx.z = K-half.
// ---------------------------------------------------------------------------
#define FC_LOAD(k0) do {                                                        \
    if (av) { const float4 va_ = *(const float4*)(ap + (k0));                   \
        astg[0]=va_.x; astg[1]=va_.y; astg[2]=va_.z; astg[3]=va_.w; }           \
    else { astg[0]=astg[1]=astg[2]=astg[3]=0.f; }                               \
    const float4 vb0_ = *(const float4*)(bp + (k0));                            \
    const float4 vb1_ = *(const float4*)(bp + (k0) + 4);                        \
    bstg[0]=vb0_.x; bstg[1]=vb0_.y; bstg[2]=vb0_.z; bstg[3]=vb0_.w;             \
    bstg[4]=vb1_.x; bstg[5]=vb1_.y; bstg[6]=vb1_.z; bstg[7]=vb1_.w;             \
} while (0)

#define FC_STORE(bf) do {                                                       \
    _Pragma("unroll")                                                           \
    for (int j_ = 0; j_ < 4; j_++) As[bf][ak + j_][arow] = astg[j_];            \
    _Pragma("unroll")                                                           \
    for (int j_ = 0; j_ < 8; j_++) Bs[bf][bk + j_][brow] = bstg[j_];            \
} while (0)

#define FC_COMPUTE(bf) do {                                                     \
    _Pragma("unroll")                                                           \
    for (int kk = 0; kk < 16; kk++) {                                           \
        float4 av_ = *(const float4*)&As[bf][kk][ty4];                          \
        float4 b0_ = *(const float4*)&Bs[bf][kk][tx8];                          \
        float4 b1_ = *(const float4*)&Bs[bf][kk][tx8 + 4];                      \
        float aa_[4] = {av_.x, av_.y, av_.z, av_.w};                            \
        float bbv_[8] = {b0_.x, b0_.y, b0_.z, b0_.w, b1_.x, b1_.y, b1_.z, b1_.w}; \
        _Pragma("unroll")                                                       \
        for (int i2 = 0; i2 < 4; i2++)                                          \
            _Pragma("unroll")                                                   \
            for (int j2 = 0; j2 < 8; j2++)                                      \
                acc[i2][j2] = fmaf(aa_[i2], bbv_[j2], acc[i2][j2]);             \
    }                                                                           \
} while (0)

__global__ void __launch_bounds__(256) fc_gemm(const float* __restrict__ fw)
{
    __shared__ __align__(16) float As[2][16][68];
    __shared__ __align__(16) float Bs[2][16][132];

    int n0 = blockIdx.x * 128;
    int m0 = blockIdx.y * 64;
    int kidx = blockIdx.z;
    int kbase = kidx * 6272;
    int t = threadIdx.x;

    int arow = t >> 2, ak = (t & 3) * 4;
    int brow = t >> 1, bk = (t & 1) * 8;
    bool av = (m0 + arow) < 600;
    const float* ap = g_rf + (size_t)(m0 + arow) * 12544 + kbase + ak;
    const float* bp = fw   + (size_t)(n0 + brow) * 12544 + kbase + bk;

    int tx8 = (t & 15) * 8;
    int ty4 = (t >> 4) * 4;

    float acc[4][8];
#pragma unroll
    for (int i = 0; i < 4; i++)
#pragma unroll
        for (int j = 0; j < 8; j++) acc[i][j] = 0.f;

    float astg[4], bstg[8];

    FC_LOAD(0);
    FC_STORE(0);
    __syncthreads();

    int buf = 0;
    for (int k0 = 16; k0 < 6272; k0 += 16) {
        FC_LOAD(k0);
        FC_COMPUTE(buf);
        FC_STORE(buf ^ 1);
        __syncthreads();
        buf ^= 1;
    }
    FC_COMPUTE(buf);

    float* part = g_fcpart + (size_t)kidx * 600 * 1408;
#pragma unroll
    for (int i = 0; i < 4; i++) {
        int m = m0 + (ty4 >> 2) * 4 + i;
        if (m >= 600) continue;
#pragma unroll
        for (int j = 0; j < 8; j++) {
            int n = n0 + tx8 + j;
            part[(size_t)m * 1408 + n] = acc[i][j];
        }
    }
}

__global__ void fc_reduce(const float* __restrict__ fb, float* __restrict__ out)
{
    int i = blockIdx.x * 256 + threadIdx.x;
    if (i >= 600 * 1408) return;
    out[i] = g_fcpart[i] + g_fcpart[600 * 1408 + i] + __ldg(&fb[i % 1408]);
}

// ---------------------------------------------------------------------------
// Launch
// ---------------------------------------------------------------------------
extern "C" void kernel_launch(void* const* d_in, const int* in_sizes, int n_in,
                              void* d_out, int out_size)
{
    const float* feat[4] = {(const float*)d_in[0], (const float*)d_in[1],
                            (const float*)d_in[2], (const float*)d_in[3]};
    const float* conv_w = (const float*)d_in[4];
    const float* conv_b = (const float*)d_in[5];
    const float* cls_w  = (const float*)d_in[6];
    const float* cls_b  = (const float*)d_in[7];
    const float* bbox_w = (const float*)d_in[8];
    const float* bbox_b = (const float*)d_in[9];
    const float* fc_w   = (const float*)d_in[10];
    const float* fc_b   = (const float*)d_in[11];

    prep_wT<<<2304, 256>>>(conv_w);
    prep_ft3<<<(BATCH * 169 * 256 + 255) / 256, 256>>>(feat[3]);

    const int Ws[4]    = {104, 52, 26, 13};
    const int noffs[4] = {0, 32448, 40560, 42588};
    for (int l = 0; l < 4; l++) {
        int W = Ws[l], H = W, Np = W * W;
        dim3 gc((Np + 127) / 128, 4, BATCH);
        conv3x3_gemm<<<gc, 256>>>(feat[l], conv_b, H, W, Np);
        dim3 gh((Np + 63) / 64, BATCH);
        head1x1<<<gh, 256>>>(cls_w, cls_b, bbox_w, bbox_b, Np, noffs[l]);
    }

    topk_select<<<8, 512>>>();
    decode_cand<<<(BATCH * TOTC + 255) / 256, 256>>>();
    nms_kernel<<<BATCH, NMSTH>>>();
    roi_align_kernel<<<BATCH * POST, 256>>>();
    fc_gemm<<<dim3(1408 / 128, (600 + 63) / 64, 2), 256>>>(fc_w);
    fc_reduce<<<(600 * 1408 + 255) / 256, 256>>>(fc_b, (float*)d_out);
}

// round 5
// speedup vs baseline: 1.2722x; 1.2475x over previous
#include <cuda_runtime.h>
#include <math.h>

// ---------------------------------------------------------------------------
// Fixed problem shapes
// ---------------------------------------------------------------------------
#define BATCH 2
#define CHN   256
#define NTOT  43095
#define TOTC  3507
#define POST  300
#define NEGF  (-1e30f)
#define CLAMPF 4.135166556742356f
#define IMG   832.0f

__device__ __constant__ int   c_W[4]      = {104, 52, 26, 13};
__device__ __constant__ int   c_Nanch[4]  = {32448, 8112, 2028, 507};
__device__ __constant__ int   c_noff[4]   = {0, 32448, 40560, 42588};
__device__ __constant__ int   c_K[4]      = {1000, 1000, 1000, 507};
__device__ __constant__ int   c_cbase[4]  = {0, 1000, 2000, 3000};
__device__ __constant__ float c_stride[4] = {8.f, 16.f, 32.f, 64.f};
__device__ __constant__ float c_size[4]   = {32.f, 64.f, 128.f, 256.f};
// conv pixel-tile (128 px) prefix: {85,22,6,2} tiles per level
__device__ __constant__ int   c_PTO[4]    = {0, 85, 107, 113};
// head pixel-tile (64 px) prefix: {169,43,11,3}
__device__ __constant__ int   c_HTO[4]    = {0, 169, 212, 223};
// g_t per-level float offsets (2 batches x 256 ch x Np each)
__device__ __constant__ int   c_toff[4]   = {0, 5537792, 6922240, 7268352};

// ---------------------------------------------------------------------------
// Static device scratch
// ---------------------------------------------------------------------------
__device__ __align__(16) float g_t[7354880];               // conv+relu out, all levels
__device__ __align__(16) float g_wT[2304 * CHN];           // conv w, [tap*256+ci][co]
__device__ __align__(16) float g_ft3[BATCH * 169 * CHN];   // feat3 channels-last
__device__ float g_logits[BATCH * NTOT];
__device__ float g_deltas[BATCH * NTOT * 4];
__device__ int   g_cand_n[BATCH * TOTC];
__device__ float g_sc[BATCH * TOTC];
__device__ float g_box[BATCH * TOTC * 4];
__device__ float g_obox[BATCH * TOTC * 4];
__device__ float g_rois[BATCH * POST * 4];
__device__ __align__(16) float g_rf[600 * 12544];
__device__ __align__(16) float g_fcpart[4 * 600 * 1408];   // split-K partials

// ---------------------------------------------------------------------------
// Prep kernels
// ---------------------------------------------------------------------------
__global__ void prep_wT(const float* __restrict__ cw)
{
    int kp = blockIdx.x;        // kp = r*256 + ci
    int co = threadIdx.x;
    int r  = kp >> 8;
    int ci = kp & 255;
    g_wT[kp * 256 + co] = cw[co * 2304 + ci * 9 + r];
}

__global__ void prep_ft3(const float* __restrict__ f3)
{
    int idx = blockIdx.x * 256 + threadIdx.x;
    if (idx >= BATCH * 169 * 256) return;
    int c = idx & 255;
    int p = (idx >> 8) % 169;
    int b = idx / (169 * 256);
    g_ft3[idx] = f3[(b * 256 + c) * 169 + p];
}

__global__ void zinit()
{
    int i = blockIdx.x * 256 + threadIdx.x;
    if (i < BATCH * POST * 4) g_rois[i] = 0.f;
}

// ---------------------------------------------------------------------------
// Conv 3x3 (+bias,+ReLU) as implicit GEMM, ALL levels in one launch.
// K reordered as k' = tap*256 + ci. Tile 64(co) x 128(px), 256 thr,
// 4x8 micro, BK=16, double-buffered smem.
// ---------------------------------------------------------------------------
#define CONV_LOAD(k0) do {                                                      \
    const float4 wv = *(const float4*)(g_wT + (size_t)((k0) + a_k) * 256 + co0 + a_c); \
    astg[0] = wv.x; astg[1] = wv.y; astg[2] = wv.z; astg[3] = wv.w;             \
    int r_ = (k0) >> 8;                                                         \
    int dy_ = r_ / 3, dx_ = r_ - dy_ * 3;                                       \
    bool vld_ = ((vmy >> dy_) & 1u) && ((vmx >> dx_) & 1u);                     \
    const float* bptr_ = inb + (size_t)(((k0) & 255) + kh) * HW + base          \
                             + (dy_ - 1) * W + (dx_ - 1);                       \
    _Pragma("unroll")                                                           \
    for (int i_ = 0; i_ < 8; i_++)                                              \
        bstg[i_] = vld_ ? __ldg(bptr_ + (size_t)i_ * 2 * HW) : 0.f;             \
} while (0)

#define CONV_STORE(bf) do {                                                     \
    *(float4*)&As[bf][a_k][a_c] = make_float4(astg[0], astg[1], astg[2], astg[3]); \
    _Pragma("unroll")                                                           \
    for (int i_ = 0; i_ < 8; i_++) Bs[bf][kh + 2 * i_][pp] = bstg[i_];          \
} while (0)

#define CONV_COMPUTE(bf) do {                                                   \
    _Pragma("unroll")                                                           \
    for (int kk = 0; kk < 16; kk++) {                                           \
        float4 av = *(const float4*)&As[bf][kk][ty4];                           \
        float4 b0 = *(const float4*)&Bs[bf][kk][tx8];                           \
        float4 b1 = *(const float4*)&Bs[bf][kk][tx8 + 4];                       \
        float aa[4] = {av.x, av.y, av.z, av.w};                                 \
        float bbv[8] = {b0.x, b0.y, b0.z, b0.w, b1.x, b1.y, b1.z, b1.w};        \
        _Pragma("unroll")                                                       \
        for (int i2 = 0; i2 < 4; i2++)                                          \
            _Pragma("unroll")                                                   \
            for (int j2 = 0; j2 < 8; j2++)                                      \
                acc[i2][j2] = fmaf(aa[i2], bbv[j2], acc[i2][j2]);               \
    }                                                                           \
} while (0)

__global__ void __launch_bounds__(256) conv_all(
    const float* __restrict__ f0, const float* __restrict__ f1,
    const float* __restrict__ f2, const float* __restrict__ f3,
    const float* __restrict__ bias)
{
    __shared__ __align__(16) float As[2][16][64];
    __shared__ __align__(16) float Bs[2][16][128];

    int bx = blockIdx.x;
    int lvl = (bx < 85) ? 0 : (bx < 107) ? 1 : (bx < 113) ? 2 : 3;
    int p0 = (bx - c_PTO[lvl]) * 128;
    int W  = c_W[lvl];
    int H  = W;
    int Np = W * W;
    int HW = Np;
    const float* in = (lvl == 0) ? f0 : (lvl == 1) ? f1 : (lvl == 2) ? f2 : f3;

    int b   = blockIdx.z;
    int co0 = blockIdx.y * 64;
    int t   = threadIdx.x;

    const float* inb = in + (size_t)b * CHN * HW;

    int pp = t & 127;
    int kh = t >> 7;
    int pix = p0 + pp;
    bool inp = pix < Np;
    int py = inp ? (pix / W) : 0;
    int px = inp ? (pix - py * W) : 0;
    int base = py * W + px;
    unsigned vmy = ((py > 0) ? 1u : 0u) | 2u | ((py + 1 < H) ? 4u : 0u);
    unsigned vmx = ((px > 0) ? 1u : 0u) | 2u | ((px + 1 < W) ? 4u : 0u);
    if (!inp) vmy = 0u;

    int a_k = t >> 4;
    int a_c = (t & 15) * 4;
    int tx8 = (t & 15) * 8;
    int ty4 = (t >> 4) * 4;

    float acc[4][8];
#pragma unroll
    for (int i = 0; i < 4; i++)
#pragma unroll
        for (int j = 0; j < 8; j++) acc[i][j] = 0.f;

    float astg[4], bstg[8];

    CONV_LOAD(0);
    CONV_STORE(0);
    __syncthreads();

    int buf = 0;
    for (int k0 = 16; k0 < 2304; k0 += 16) {
        CONV_LOAD(k0);
        CONV_COMPUTE(buf);
        CONV_STORE(buf ^ 1);
        __syncthreads();
        buf ^= 1;
    }
    CONV_COMPUTE(buf);

#pragma unroll
    for (int i = 0; i < 4; i++) {
        int co = co0 + (ty4 >> 2) * 4 + i;
        float bi = __ldg(&bias[co]);
        float* op = g_t + c_toff[lvl] + ((size_t)b * CHN + co) * Np;
#pragma unroll
        for (int j = 0; j < 8; j++) {
            int p = p0 + tx8 + j;
            if (p < Np) op[p] = fmaxf(acc[i][j] + bi, 0.f);
        }
    }
}

// ---------------------------------------------------------------------------
// 1x1 heads, all levels one launch: 64 px/block, 4 channel-quarters, reduce.
// ---------------------------------------------------------------------------
__global__ void __launch_bounds__(256) head_all(
    const float* __restrict__ cls_w, const float* __restrict__ cls_b,
    const float* __restrict__ bbox_w, const float* __restrict__ bbox_b)
{
    __shared__ float w[15][256];
    __shared__ float red[4][15][65];

    int bx = blockIdx.x;
    int lvl = (bx < 169) ? 0 : (bx < 212) ? 1 : (bx < 223) ? 2 : 3;
    int pt = bx - c_HTO[lvl];
    int Wl = c_W[lvl];
    int Np = Wl * Wl;
    int noff = c_noff[lvl];

    int b = blockIdx.y;
    int t = threadIdx.x;
    for (int i = t; i < 15 * 256; i += 256) {
        int o = i >> 8, c = i & 255;
        w[o][c] = (o < 3) ? cls_w[o * 256 + c] : bbox_w[(o - 3) * 256 + c];
    }
    __syncthreads();

    int pl = t & 63, cq = t >> 6;
    int p = pt * 64 + pl;
    float acc[15];
#pragma unroll
    for (int o = 0; o < 15; o++) acc[o] = 0.f;

    if (p < Np) {
        const float* tb = g_t + c_toff[lvl] + ((size_t)b * CHN + cq * 64) * Np + p;
#pragma unroll 4
        for (int c = 0; c < 64; c++) {
            float v = __ldg(tb + (size_t)c * Np);
#pragma unroll
            for (int o = 0; o < 15; o++) acc[o] = fmaf(w[o][cq * 64 + c], v, acc[o]);
        }
    }
#pragma unroll
    for (int o = 0; o < 15; o++) red[cq][o][pl] = acc[o];
    __syncthreads();

    for (int idx = t; idx < 64 * 15; idx += 256) {
        int pl2 = idx & 63, o = idx >> 6;
        int p2 = pt * 64 + pl2;
        if (p2 >= Np) continue;
        float s = red[0][o][pl2] + red[1][o][pl2] + red[2][o][pl2] + red[3][o][pl2];
        int nb = b * NTOT + noff + p2 * 3;
        if (o < 3) {
            g_logits[nb + o] = s + __ldg(&cls_b[o]);
        } else {
            int oo = o - 3;
            int a = oo >> 2, j = oo & 3;
            g_deltas[(size_t)(nb + a) * 4 + j] = s + __ldg(&bbox_b[oo]);
        }
    }
}

// ---------------------------------------------------------------------------
// Radix top-k select per (batch, level). Unordered set is safe.
// ---------------------------------------------------------------------------
__device__ __forceinline__ unsigned fkey(float f)
{
    unsigned u = __float_as_uint(f);
    return (u & 0x80000000u) ? ~u : (u | 0x80000000u);
}

__global__ void __launch_bounds__(512) topk_select()
{
    int blk = blockIdx.x;
    int b = blk >> 2, lvl = blk & 3;
    int N = c_Nanch[lvl], K = c_K[lvl];
    const float* lg = g_logits + b * NTOT + c_noff[lvl];

    __shared__ unsigned bins[256];
    __shared__ unsigned s_prefix, s_kk, s_cG, s_c1, s_c2;
    int t = threadIdx.x;
    if (t == 0) { s_prefix = 0u; s_kk = (unsigned)K; }
    __syncthreads();

    for (int pass = 3; pass >= 0; pass--) {
        int sh = pass * 8;
        if (t < 256) bins[t] = 0u;
        __syncthreads();
        unsigned prefix = s_prefix;
        unsigned hmask = (pass == 3) ? 0u : (0xFFFFFFFFu << (sh + 8));
        for (int i = t; i < N; i += 512) {
            unsigned key = fkey(lg[i]);
            if ((key & hmask) == prefix)
                atomicAdd(&bins[(key >> sh) & 255u], 1u);
        }
        __syncthreads();
        if (t == 0) {
            unsigned kk = s_kk, cum = 0u;
            int v = 255;
            for (; v > 0; v--) {
                if (cum + bins[v] >= kk) break;
                cum += bins[v];
            }
            s_kk = kk - cum;
            s_prefix = prefix | ((unsigned)v << sh);
        }
        __syncthreads();
    }
    unsigned T = s_prefix;
    if (t == 0) { s_cG = 0u; s_c1 = 0u; s_c2 = 0u; }
    __syncthreads();

    unsigned lc = 0u;
    for (int i = t; i < N; i += 512)
        if (fkey(lg[i]) > T) lc++;
    if (lc) atomicAdd(&s_cG, lc);
    __syncthreads();
    unsigned TG = s_cG;

    int* outn = g_cand_n + b * TOTC + c_cbase[lvl];
    for (int i = t; i < N; i += 512) {
        unsigned key = fkey(lg[i]);
        if (key > T) {
            unsigned s = atomicAdd(&s_c1, 1u);
            outn[s] = i;
        } else if (key == T) {
            unsigned s = TG + atomicAdd(&s_c2, 1u);
            if (s < (unsigned)K) outn[s] = i;
        }
    }
}

// ---------------------------------------------------------------------------
// Decode candidates
// ---------------------------------------------------------------------------
__global__ void __launch_bounds__(256) decode_cand()
{
    int tid = blockIdx.x * 256 + threadIdx.x;
    if (tid >= BATCH * TOTC) return;
    int b = tid / TOTC, c = tid - b * TOTC;
    int lvl = c / 1000; if (lvl > 3) lvl = 3;
    int n = g_cand_n[tid];
    int W = c_W[lvl];
    float stride = c_stride[lvl], size = c_size[lvl];

    int a = n % 3, cell = n / 3;
    int gx = cell % W, gy = cell / W;

    float ratio = (a == 0) ? 0.5f : ((a == 1) ? 1.0f : 2.0f);
    float hr = sqrtf(ratio);
    float wr = 1.0f / hr;
    float ws = wr * size, hs = hr * size;
    float w2 = rintf(ws * 0.5f);
    float h2 = rintf(hs * 0.5f);
    float sx = gx * stride, sy = gy * stride;
    float x1 = sx - w2, y1 = sy - h2, x2 = sx + w2, y2 = sy + h2;

    float wa = x2 - x1, ha = y2 - y1;
    float cxa = x1 + 0.5f * wa, cya = y1 + 0.5f * ha;

    int gi = b * NTOT + c_noff[lvl] + n;
    float score = g_logits[gi];
    const float* d = g_deltas + (size_t)gi * 4;
    float dx = d[0], dy = d[1];
    float dw = fminf(d[2], CLAMPF), dh = fminf(d[3], CLAMPF);
    float cx = dx * wa + cxa, cy = dy * ha + cya;
    float bw = expf(dw) * wa, bh = expf(dh) * ha;
    float bx1 = cx - 0.5f * bw, by1 = cy - 0.5f * bh;
    float bx2 = cx + 0.5f * bw, by2 = cy + 0.5f * bh;
    bx1 = fminf(fmaxf(bx1, 0.f), IMG);
    by1 = fminf(fmaxf(by1, 0.f), IMG);
    bx2 = fminf(fmaxf(bx2, 0.f), IMG);
    by2 = fminf(fmaxf(by2, 0.f), IMG);

    float bws = bx2 - bx1, bhs = by2 - by1;
    bool bad = (bws < 0.001f) || (bhs < 0.001f) || (score < 0.0f);
    g_sc[tid] = bad ? NEGF : score;

    float off = (float)lvl * 4096.0f;
    float* bp = g_box + (size_t)tid * 4;
    bp[0] = bx1; bp[1] = by1; bp[2] = bx2; bp[3] = by2;
    float* op = g_obox + (size_t)tid * 4;
    op[0] = bx1 + off; op[1] = by1 + off; op[2] = bx2 + off; op[3] = by2 + off;
}

// ---------------------------------------------------------------------------
// Greedy NMS
// ---------------------------------------------------------------------------
#define NMSTH 512
#define NMSLP 7

__global__ void __launch_bounds__(NMSTH) nms_kernel()
{
    int b = blockIdx.x;
    int t = threadIdx.x;

    float sc[NMSLP], ax[NMSLP], ay[NMSLP], bx2[NMSLP], by2[NMSLP], ar[NMSLP];
#pragma unroll
    for (int l = 0; l < NMSLP; l++) {
        int i = t + l * NMSTH;
        if (i < TOTC) {
            sc[l] = g_sc[b * TOTC + i];
            const float* bbp = g_obox + (size_t)(b * TOTC + i) * 4;
            ax[l] = bbp[0]; ay[l] = bbp[1]; bx2[l] = bbp[2]; by2[l] = bbp[3];
            ar[l] = (bx2[l] - ax[l]) * (by2[l] - ay[l]);
        } else {
            sc[l] = -INFINITY; ax[l] = ay[l] = bx2[l] = by2[l] = 0.f; ar[l] = 0.f;
        }
    }

    __shared__ unsigned long long s_best[2];
    __shared__ float bb[6];
    if (t == 0) { s_best[0] = 0ull; s_best[1] = 0ull; }
    __syncthreads();

    for (int it = 0; it < POST; it++) {
        unsigned long long key = 0ull;
#pragma unroll
        for (int l = 0; l < NMSLP; l++) {
            unsigned idx = (unsigned)(t + l * NMSTH);
            unsigned long long kl2 = ((unsigned long long)fkey(sc[l]) << 32)
                                   | (unsigned long long)(0x7FFFFFFFu - idx);
            if (kl2 > key) key = kl2;
        }
#pragma unroll
        for (int o = 16; o; o >>= 1) {
            unsigned long long ok2 = __shfl_down_sync(0xFFFFFFFFu, key, o);
            if (ok2 > key) key = ok2;
        }
        if ((t & 31) == 0) atomicMax(&s_best[it & 1], key);
        __syncthreads();

        unsigned long long bk = s_best[it & 1];
        int j = (int)(0x7FFFFFFFu - (unsigned)(bk & 0xFFFFFFFFull));

        int lo = j - t;
        if (lo >= 0 && (lo & (NMSTH - 1)) == 0) {
            int l = lo >> 9;
            if (l < NMSLP) {
                bb[0] = ax[l]; bb[1] = ay[l]; bb[2] = bx2[l]; bb[3] = by2[l];
                bb[4] = ar[l]; bb[5] = sc[l];
                sc[l] = NEGF;
            }
        }
        if (t == 0) s_best[(it + 1) & 1] = 0ull;
        __syncthreads();

        float jx1 = bb[0], jy1 = bb[1], jx2 = bb[2], jy2 = bb[3], ja = bb[4];
        bool ok = bb[5] > NEGF * 0.5f;
        if (t == 0) {
            float* rr = g_rois + (size_t)(b * POST + it) * 4;
            if (ok) {
                const float* cb = g_box + (size_t)(b * TOTC + j) * 4;
                rr[0] = cb[0]; rr[1] = cb[1]; rr[2] = cb[2]; rr[3] = cb[3];
            } else {
                rr[0] = 0.f; rr[1] = 0.f; rr[2] = 0.f; rr[3] = 0.f;
            }
        }
#pragma unroll
        for (int l = 0; l < NMSLP; l++) {
            float xx1 = fmaxf(jx1, ax[l]),  yy1 = fmaxf(jy1, ay[l]);
            float xx2 = fminf(jx2, bx2[l]), yy2 = fminf(jy2, by2[l]);
            float inter = fmaxf(xx2 - xx1, 0.f) * fmaxf(yy2 - yy1, 0.f);
            float iou = inter / fmaxf(ja + ar[l] - inter, 1e-9f);
            if (iou > 0.7f) sc[l] = NEGF;
        }
    }
}

// ---------------------------------------------------------------------------
// ROI align on feat3 (13x13 channels-last), 7x7 out, sampling 2
// ---------------------------------------------------------------------------
__global__ void __launch_bounds__(256) roi_align_kernel()
{
    int roi = blockIdx.x;
    int b = roi / POST;
    int c = threadIdx.x;

    const float* R = g_rois + (size_t)roi * 4;
    const float scale = 0.015625f;
    float x1 = R[0] * scale - 0.5f, y1 = R[1] * scale - 0.5f;
    float x2 = R[2] * scale - 0.5f, y2 = R[3] * scale - 0.5f;

    float acc[49];
#pragma unroll
    for (int i = 0; i < 49; i++) acc[i] = 0.f;

    const float* F = g_ft3 + (size_t)b * 169 * 256 + c;

#pragma unroll
    for (int py = 0; py < 14; py++) {
        float gy = ((float)py + 0.5f) / 14.0f;
        float yy = y1 + gy * (y2 - y1);
        bool vy = (yy >= -1.0f) && (yy <= 13.0f);
        float y = fminf(fmaxf(yy, 0.f), 12.f);
        int y0 = (int)floorf(y);
        int y1i = min(y0 + 1, 12);
        float ly = y - (float)y0;
#pragma unroll
        for (int px = 0; px < 14; px++) {
            float gx = ((float)px + 0.5f) / 14.0f;
            float xx = x1 + gx * (x2 - x1);
            bool vx = (xx >= -1.0f) && (xx <= 13.0f);
            float x = fminf(fmaxf(xx, 0.f), 12.f);
            int x0 = (int)floorf(x);
            int x1i = min(x0 + 1, 12);
            float lx = x - (float)x0;

            float c00 = __ldg(&F[(y0 * 13 + x0) * 256]);
            float c01 = __ldg(&F[(y0 * 13 + x1i) * 256]);
            float c10 = __ldg(&F[(y1i * 13 + x0) * 256]);
            float c11 = __ldg(&F[(y1i * 13 + x1i) * 256]);
            float v = c00 * (1.f - ly) * (1.f - lx) + c01 * (1.f - ly) * lx
                    + c10 * ly * (1.f - lx)        + c11 * ly * lx;
            if (!(vy && vx)) v = 0.f;
            acc[(py >> 1) * 7 + (px >> 1)] += v;
        }
    }

    float* out = g_rf + (size_t)roi * 12544 + c * 49;
#pragma unroll
    for (int i = 0; i < 49; i++) out[i] = acc[i] * 0.25f;
}

// ---------------------------------------------------------------------------
// FC split-K GEMM (K split 4 ways): 64(m) x 128(n), BK=16, double-buffered.
// ---------------------------------------------------------------------------
#define FC_LOAD(k0) do {                                                        \
    if (av) { const float4 va_ = *(const float4*)(ap + (k0));                   \
        astg[0]=va_.x; astg[1]=va_.y; astg[2]=va_.z; astg[3]=va_.w; }           \
    else { astg[0]=astg[1]=astg[2]=astg[3]=0.f; }                               \
    const float4 vb0_ = *(const float4*)(bp + (k0));                            \
    const float4 vb1_ = *(const float4*)(bp + (k0) + 4);                        \
    bstg[0]=vb0_.x; bstg[1]=vb0_.y; bstg[2]=vb0_.z; bstg[3]=vb0_.w;             \
    bstg[4]=vb1_.x; bstg[5]=vb1_.y; bstg[6]=vb1_.z; bstg[7]=vb1_.w;             \
} while (0)

#define FC_STORE(bf) do {                                                       \
    _Pragma("unroll")                                                           \
    for (int j_ = 0; j_ < 4; j_++) As[bf][ak + j_][arow] = astg[j_];            \
    _Pragma("unroll")                                                           \
    for (int j_ = 0; j_ < 8; j_++) Bs[bf][bk + j_][brow] = bstg[j_];            \
} while (0)

#define FC_COMPUTE(bf) do {                                                     \
    _Pragma("unroll")                                                           \
    for (int kk = 0; kk < 16; kk++) {                                           \
        float4 av_ = *(const float4*)&As[bf][kk][ty4];                          \
        float4 b0_ = *(const float4*)&Bs[bf][kk][tx8];                          \
        float4 b1_ = *(const float4*)&Bs[bf][kk][tx8 + 4];                      \
        float aa_[4] = {av_.x, av_.y, av_.z, av_.w};                            \
        float bbv_[8] = {b0_.x, b0_.y, b0_.z, b0_.w, b1_.x, b1_.y, b1_.z, b1_.w}; \
        _Pragma("unroll")                                                       \
        for (int i2 = 0; i2 < 4; i2++)                                          \
            _Pragma("unroll")                                                   \
            for (int j2 = 0; j2 < 8; j2++)                                      \
                acc[i2][j2] = fmaf(aa_[i2], bbv_[j2], acc[i2][j2]);             \
    }                                                                           \
} while (0)

__global__ void __launch_bounds__(256) fc_gemm(const float* __restrict__ fw)
{
    __shared__ __align__(16) float As[2][16][68];
    __shared__ __align__(16) float Bs[2][16][132];

    int n0 = blockIdx.x * 128;
    int m0 = blockIdx.y * 64;
    int kidx = blockIdx.z;
    int kbase = kidx * 3136;          // 12544 / 4
    int t = threadIdx.x;

    int arow = t >> 2, ak = (t & 3) * 4;
    int brow = t >> 1, bk = (t & 1) * 8;
    bool av = (m0 + arow) < 600;
    const float* ap = g_rf + (size_t)(m0 + arow) * 12544 + kbase + ak;
    const float* bp = fw   + (size_t)(n0 + brow) * 12544 + kbase + bk;

    int tx8 = (t & 15) * 8;
    int ty4 = (t >> 4) * 4;

    float acc[4][8];
#pragma unroll
    for (int i = 0; i < 4; i++)
#pragma unroll
        for (int j = 0; j < 8; j++) acc[i][j] = 0.f;

    float astg[4], bstg[8];

    FC_LOAD(0);
    FC_STORE(0);
    __syncthreads();

    int buf = 0;
    for (int k0 = 16; k0 < 3136; k0 += 16) {
        FC_LOAD(k0);
        FC_COMPUTE(buf);
        FC_STORE(buf ^ 1);
        __syncthreads();
        buf ^= 1;
    }
    FC_COMPUTE(buf);

    float* part = g_fcpart + (size_t)kidx * 600 * 1408;
#pragma unroll
    for (int i = 0; i < 4; i++) {
        int m = m0 + (ty4 >> 2) * 4 + i;
        if (m >= 600) continue;
#pragma unroll
        for (int j = 0; j < 8; j++) {
            int n = n0 + tx8 + j;
            part[(size_t)m * 1408 + n] = acc[i][j];
        }
    }
}

__global__ void fc_reduce(const float* __restrict__ fb, float* __restrict__ out)
{
    int i = blockIdx.x * 256 + threadIdx.x;
    if (i >= 600 * 1408) return;
    const int S = 600 * 1408;
    out[i] = ((g_fcpart[i] + g_fcpart[S + i])
            + (g_fcpart[2 * S + i] + g_fcpart[3 * S + i])) + __ldg(&fb[i % 1408]);
}

// ---------------------------------------------------------------------------
// Launch: conv_all deliberately placed at process-launch index 3 (the slot
// ncu has captured in both prior rounds) via zinit at index 2.
// ---------------------------------------------------------------------------
extern "C" void kernel_launch(void* const* d_in, const int* in_sizes, int n_in,
                              void* d_out, int out_size)
{
    const float* f0     = (const float*)d_in[0];
    const float* f1     = (const float*)d_in[1];
    const float* f2     = (const float*)d_in[2];
    const float* f3     = (const float*)d_in[3];
    const float* conv_w = (const float*)d_in[4];
    const float* conv_b = (const float*)d_in[5];
    const float* cls_w  = (const float*)d_in[6];
    const float* cls_b  = (const float*)d_in[7];
    const float* bbox_w = (const float*)d_in[8];
    const float* bbox_b = (const float*)d_in[9];
    const float* fc_w   = (const float*)d_in[10];
    const float* fc_b   = (const float*)d_in[11];

    prep_wT<<<2304, 256>>>(conv_w);                                   // 0
    prep_ft3<<<(BATCH * 169 * 256 + 255) / 256, 256>>>(f3);           // 1
    zinit<<<(BATCH * POST * 4 + 255) / 256, 256>>>();                 // 2
    conv_all<<<dim3(115, 4, BATCH), 256>>>(f0, f1, f2, f3, conv_b);   // 3  <- profile slot
    head_all<<<dim3(226, BATCH), 256>>>(cls_w, cls_b, bbox_w, bbox_b);// 4
    topk_select<<<8, 512>>>();                                        // 5
    decode_cand<<<(BATCH * TOTC + 255) / 256, 256>>>();               // 6
    nms_kernel<<<BATCH, NMSTH>>>();                                   // 7
    roi_align_kernel<<<BATCH * POST, 256>>>();                        // 8
    fc_gemm<<<dim3(1408 / 128, (600 + 63) / 64, 4), 256>>>(fc_w);     // 9
    fc_reduce<<<(600 * 1408 + 255) / 256, 256>>>(fc_b, (float*)d_out);// 10
}

// round 6
// speedup vs baseline: 1.6594x; 1.3043x over previous
#include <cuda_runtime.h>
#include <math.h>

// ---------------------------------------------------------------------------
// Fixed problem shapes
// ---------------------------------------------------------------------------
#define BATCH 2
#define CHN   256
#define NTOT  43095
#define TOTC  3507
#define POST  300
#define NEGF  (-1e30f)
#define CLAMPF 4.135166556742356f
#define IMG   832.0f

__device__ __constant__ int   c_W[4]      = {104, 52, 26, 13};
__device__ __constant__ int   c_Nanch[4]  = {32448, 8112, 2028, 507};
__device__ __constant__ int   c_noff[4]   = {0, 32448, 40560, 42588};
__device__ __constant__ int   c_K[4]      = {1000, 1000, 1000, 507};
__device__ __constant__ int   c_cbase[4]  = {0, 1000, 2000, 3000};
__device__ __constant__ float c_stride[4] = {8.f, 16.f, 32.f, 64.f};
__device__ __constant__ float c_size[4]   = {32.f, 64.f, 128.f, 256.f};
// conv pixel-tile (128 px) prefix: {85,22,6,2}
__device__ __constant__ int   c_PTO[4]    = {0, 85, 107, 113};
// head pixel-tile (64 px) prefix: {169,43,11,3}
__device__ __constant__ int   c_HTO[4]    = {0, 169, 212, 223};
// g_t per-level float offsets
__device__ __constant__ int   c_toff[4]   = {0, 5537792, 6922240, 7268352};

// ---------------------------------------------------------------------------
// Static device scratch
// ---------------------------------------------------------------------------
__device__ __align__(16) float g_t[7354880];
__device__ __align__(16) float g_wT[2304 * CHN];           // [tap*256+ci][co]
__device__ __align__(16) float g_ft3[BATCH * 169 * CHN];
__device__ float g_logits[BATCH * NTOT];
__device__ float g_deltas[BATCH * NTOT * 4];
__device__ int   g_cand_n[BATCH * TOTC];
__device__ float g_sc[BATCH * TOTC];
__device__ float g_box[BATCH * TOTC * 4];
__device__ float g_obox[BATCH * TOTC * 4];
__device__ float g_rois[BATCH * POST * 4];
__device__ __align__(16) float g_rf[600 * 12544];
__device__ __align__(16) float g_fcpart[4 * 600 * 1408];

// ---------------------------------------------------------------------------
// Prep kernels
// ---------------------------------------------------------------------------
__global__ void prep_wT(const float* __restrict__ cw)
{
    int kp = blockIdx.x;        // kp = r*256 + ci
    int co = threadIdx.x;
    int r  = kp >> 8;
    int ci = kp & 255;
    g_wT[kp * 256 + co] = cw[co * 2304 + ci * 9 + r];
}

__global__ void prep_ft3(const float* __restrict__ f3)
{
    int idx = blockIdx.x * 256 + threadIdx.x;
    if (idx >= BATCH * 169 * 256) return;
    int c = idx & 255;
    int p = (idx >> 8) % 169;
    int b = idx / (169 * 256);
    g_ft3[idx] = f3[(b * 256 + c) * 169 + p];
}

__global__ void zinit()
{
    int i = blockIdx.x * 256 + threadIdx.x;
    if (i < BATCH * POST * 4) g_rois[i] = 0.f;
}

// ---------------------------------------------------------------------------
// Conv 3x3 (+bias,+ReLU) implicit GEMM, all levels, k' = tap*256 + ci.
// Tile 128(co) x 128(px), 256 threads, 8x8 micro (split fragments),
// BK=8 double-buffered. 4 LDS.128 per 64 FMA -> FMA-bound.
// ---------------------------------------------------------------------------
#define CONV_LOAD(k0) do {                                                      \
    wstg = *(const float4*)(g_wT + (size_t)((k0) + akk) * 256 + co0 + ac4);     \
    int r_ = (k0) >> 8;                                                         \
    int dy_ = r_ / 3, dx_ = r_ - dy_ * 3;                                       \
    int ciHW_ = (((k0) & 255) + bkk) * HW;                                      \
    int off_ = ciHW_ + (dy_ - 1) * W + (dx_ - 1);                               \
    _Pragma("unroll")                                                           \
    for (int i_ = 0; i_ < 4; i_++) {                                            \
        bool v_ = ((vmy[i_] >> dy_) & 1u) && ((vmx[i_] >> dx_) & 1u);           \
        bstg[i_] = v_ ? __ldg(inb + off_ + pbase[i_]) : 0.f;                    \
    }                                                                           \
} while (0)

#define CONV_STORE(bf) do {                                                     \
    *(float4*)&As[bf][akk][ac4] = wstg;                                         \
    *(float4*)&Bs[bf][bkk][bp4] = make_float4(bstg[0], bstg[1], bstg[2], bstg[3]); \
} while (0)

#define CONV_COMPUTE(bf) do {                                                   \
    _Pragma("unroll")                                                           \
    for (int kk = 0; kk < 8; kk++) {                                            \
        float4 a0 = *(const float4*)&As[bf][kk][ty4];                           \
        float4 a1 = *(const float4*)&As[bf][kk][64 + ty4];                      \
        float4 b0 = *(const float4*)&Bs[bf][kk][tx4];                           \
        float4 b1 = *(const float4*)&Bs[bf][kk][64 + tx4];                      \
        float aa[8] = {a0.x, a0.y, a0.z, a0.w, a1.x, a1.y, a1.z, a1.w};         \
        float bbv[8] = {b0.x, b0.y, b0.z, b0.w, b1.x, b1.y, b1.z, b1.w};        \
        _Pragma("unroll")                                                       \
        for (int i2 = 0; i2 < 8; i2++)                                          \
            _Pragma("unroll")                                                   \
            for (int j2 = 0; j2 < 8; j2++)                                      \
                acc[i2][j2] = fmaf(aa[i2], bbv[j2], acc[i2][j2]);               \
    }                                                                           \
} while (0)

__global__ void __launch_bounds__(256, 2) conv_all(
    const float* __restrict__ f0, const float* __restrict__ f1,
    const float* __restrict__ f2, const float* __restrict__ f3,
    const float* __restrict__ bias)
{
    __shared__ __align__(16) float As[2][8][128];
    __shared__ __align__(16) float Bs[2][8][128];

    int bx = blockIdx.x;
    int lvl = (bx < 85) ? 0 : (bx < 107) ? 1 : (bx < 113) ? 2 : 3;
    int p0 = (bx - c_PTO[lvl]) * 128;
    int W  = c_W[lvl];
    int H  = W;
    int Np = W * W;
    int HW = Np;
    const float* in = (lvl == 0) ? f0 : (lvl == 1) ? f1 : (lvl == 2) ? f2 : f3;

    int b   = blockIdx.z;
    int co0 = blockIdx.y * 128;
    int t   = threadIdx.x;

    const float* inb = in + (size_t)b * CHN * HW;

    // B gather mapping: k-row bkk, 4 consecutive pixels
    int bkk = t >> 5;
    int bp4 = (t & 31) * 4;
    int pbase[4];
    unsigned vmy[4], vmx[4];
#pragma unroll
    for (int i = 0; i < 4; i++) {
        int pix = p0 + bp4 + i;
        bool inp = pix < Np;
        int py = inp ? (pix / W) : 0;
        int px = inp ? (pix - py * W) : 0;
        pbase[i] = py * W + px;
        vmy[i] = ((py > 0) ? 1u : 0u) | 2u | ((py + 1 < H) ? 4u : 0u);
        vmx[i] = ((px > 0) ? 1u : 0u) | 2u | ((px + 1 < W) ? 4u : 0u);
        if (!inp) vmy[i] = 0u;
    }

    // A load mapping
    int akk = t >> 5;
    int ac4 = (t & 31) * 4;
    // compute mapping
    int tx4 = (t & 15) * 4;
    int ty4 = (t >> 4) * 4;

    float acc[8][8];
#pragma unroll
    for (int i = 0; i < 8; i++)
#pragma unroll
        for (int j = 0; j < 8; j++) acc[i][j] = 0.f;

    float4 wstg;
    float bstg[4];

    CONV_LOAD(0);
    CONV_STORE(0);
    __syncthreads();

    int buf = 0;
    for (int k0 = 8; k0 < 2304; k0 += 8) {
        CONV_LOAD(k0);
        CONV_COMPUTE(buf);
        CONV_STORE(buf ^ 1);
        __syncthreads();
        buf ^= 1;
    }
    CONV_COMPUTE(buf);

    // epilogue: bias + ReLU
#pragma unroll
    for (int i = 0; i < 8; i++) {
        int co = co0 + ((i < 4) ? (ty4 + i) : (64 + ty4 + i - 4));
        float bi = __ldg(&bias[co]);
        float* op = g_t + c_toff[lvl] + ((size_t)b * CHN + co) * Np;
#pragma unroll
        for (int j = 0; j < 8; j++) {
            int p = p0 + ((j < 4) ? (tx4 + j) : (64 + tx4 + j - 4));
            if (p < Np) op[p] = fmaxf(acc[i][j] + bi, 0.f);
        }
    }
}

// ---------------------------------------------------------------------------
// 1x1 heads, all levels: 64 px/block, 4 channel-quarters, smem reduce.
// ---------------------------------------------------------------------------
__global__ void __launch_bounds__(256) head_all(
    const float* __restrict__ cls_w, const float* __restrict__ cls_b,
    const float* __restrict__ bbox_w, const float* __restrict__ bbox_b)
{
    __shared__ float w[15][256];
    __shared__ float red[4][15][65];

    int bx = blockIdx.x;
    int lvl = (bx < 169) ? 0 : (bx < 212) ? 1 : (bx < 223) ? 2 : 3;
    int pt = bx - c_HTO[lvl];
    int Wl = c_W[lvl];
    int Np = Wl * Wl;
    int noff = c_noff[lvl];

    int b = blockIdx.y;
    int t = threadIdx.x;
    for (int i = t; i < 15 * 256; i += 256) {
        int o = i >> 8, c = i & 255;
        w[o][c] = (o < 3) ? cls_w[o * 256 + c] : bbox_w[(o - 3) * 256 + c];
    }
    __syncthreads();

    int pl = t & 63, cq = t >> 6;
    int p = pt * 64 + pl;
    float acc[15];
#pragma unroll
    for (int o = 0; o < 15; o++) acc[o] = 0.f;

    if (p < Np) {
        const float* tb = g_t + c_toff[lvl] + ((size_t)b * CHN + cq * 64) * Np + p;
#pragma unroll 4
        for (int c = 0; c < 64; c++) {
            float v = __ldg(tb + (size_t)c * Np);
#pragma unroll
            for (int o = 0; o < 15; o++) acc[o] = fmaf(w[o][cq * 64 + c], v, acc[o]);
        }
    }
#pragma unroll
    for (int o = 0; o < 15; o++) red[cq][o][pl] = acc[o];
    __syncthreads();

    for (int idx = t; idx < 64 * 15; idx += 256) {
        int pl2 = idx & 63, o = idx >> 6;
        int p2 = pt * 64 + pl2;
        if (p2 >= Np) continue;
        float s = red[0][o][pl2] + red[1][o][pl2] + red[2][o][pl2] + red[3][o][pl2];
        int nb = b * NTOT + noff + p2 * 3;
        if (o < 3) {
            g_logits[nb + o] = s + __ldg(&cls_b[o]);
        } else {
            int oo = o - 3;
            int a = oo >> 2, j = oo & 3;
            g_deltas[(size_t)(nb + a) * 4 + j] = s + __ldg(&bbox_b[oo]);
        }
    }
}

// ---------------------------------------------------------------------------
// Radix top-k select per (batch, level).
// ---------------------------------------------------------------------------
__device__ __forceinline__ unsigned fkey(float f)
{
    unsigned u = __float_as_uint(f);
    return (u & 0x80000000u) ? ~u : (u | 0x80000000u);
}

__global__ void __launch_bounds__(512) topk_select()
{
    int blk = blockIdx.x;
    int b = blk >> 2, lvl = blk & 3;
    int N = c_Nanch[lvl], K = c_K[lvl];
    const float* lg = g_logits + b * NTOT + c_noff[lvl];

    __shared__ unsigned bins[256];
    __shared__ unsigned s_prefix, s_kk, s_cG, s_c1, s_c2;
    int t = threadIdx.x;
    if (t == 0) { s_prefix = 0u; s_kk = (unsigned)K; }
    __syncthreads();

    for (int pass = 3; pass >= 0; pass--) {
        int sh = pass * 8;
        if (t < 256) bins[t] = 0u;
        __syncthreads();
        unsigned prefix = s_prefix;
        unsigned hmask = (pass == 3) ? 0u : (0xFFFFFFFFu << (sh + 8));
        for (int i = t; i < N; i += 512) {
            unsigned key = fkey(lg[i]);
            if ((key & hmask) == prefix)
                atomicAdd(&bins[(key >> sh) & 255u], 1u);
        }
        __syncthreads();
        if (t == 0) {
            unsigned kk = s_kk, cum = 0u;
            int v = 255;
            for (; v > 0; v--) {
                if (cum + bins[v] >= kk) break;
                cum += bins[v];
            }
            s_kk = kk - cum;
            s_prefix = prefix | ((unsigned)v << sh);
        }
        __syncthreads();
    }
    unsigned T = s_prefix;
    if (t == 0) { s_cG = 0u; s_c1 = 0u; s_c2 = 0u; }
    __syncthreads();

    unsigned lc = 0u;
    for (int i = t; i < N; i += 512)
        if (fkey(lg[i]) > T) lc++;
    if (lc) atomicAdd(&s_cG, lc);
    __syncthreads();
    unsigned TG = s_cG;

    int* outn = g_cand_n + b * TOTC + c_cbase[lvl];
    for (int i = t; i < N; i += 512) {
        unsigned key = fkey(lg[i]);
        if (key > T) {
            unsigned s = atomicAdd(&s_c1, 1u);
            outn[s] = i;
        } else if (key == T) {
            unsigned s = TG + atomicAdd(&s_c2, 1u);
            if (s < (unsigned)K) outn[s] = i;
        }
    }
}

// ---------------------------------------------------------------------------
// Decode candidates
// ---------------------------------------------------------------------------
__global__ void __launch_bounds__(256) decode_cand()
{
    int tid = blockIdx.x * 256 + threadIdx.x;
    if (tid >= BATCH * TOTC) return;
    int b = tid / TOTC, c = tid - b * TOTC;
    int lvl = c / 1000; if (lvl > 3) lvl = 3;
    int n = g_cand_n[tid];
    int W = c_W[lvl];
    float stride = c_stride[lvl], size = c_size[lvl];

    int a = n % 3, cell = n / 3;
    int gx = cell % W, gy = cell / W;

    float ratio = (a == 0) ? 0.5f : ((a == 1) ? 1.0f : 2.0f);
    float hr = sqrtf(ratio);
    float wr = 1.0f / hr;
    float ws = wr * size, hs = hr * size;
    float w2 = rintf(ws * 0.5f);
    float h2 = rintf(hs * 0.5f);
    float sx = gx * stride, sy = gy * stride;
    float x1 = sx - w2, y1 = sy - h2, x2 = sx + w2, y2 = sy + h2;

    float wa = x2 - x1, ha = y2 - y1;
    float cxa = x1 + 0.5f * wa, cya = y1 + 0.5f * ha;

    int gi = b * NTOT + c_noff[lvl] + n;
    float score = g_logits[gi];
    const float* d = g_deltas + (size_t)gi * 4;
    float dx = d[0], dy = d[1];
    float dw = fminf(d[2], CLAMPF), dh = fminf(d[3], CLAMPF);
    float cx = dx * wa + cxa, cy = dy * ha + cya;
    float bw = expf(dw) * wa, bh = expf(dh) * ha;
    float bx1 = cx - 0.5f * bw, by1 = cy - 0.5f * bh;
    float bx2 = cx + 0.5f * bw, by2 = cy + 0.5f * bh;
    bx1 = fminf(fmaxf(bx1, 0.f), IMG);
    by1 = fminf(fmaxf(by1, 0.f), IMG);
    bx2 = fminf(fmaxf(bx2, 0.f), IMG);
    by2 = fminf(fmaxf(by2, 0.f), IMG);

    float bws = bx2 - bx1, bhs = by2 - by1;
    bool bad = (bws < 0.001f) || (bhs < 0.001f) || (score < 0.0f);
    g_sc[tid] = bad ? NEGF : score;

    float off = (float)lvl * 4096.0f;
    float* bp = g_box + (size_t)tid * 4;
    bp[0] = bx1; bp[1] = by1; bp[2] = bx2; bp[3] = by2;
    float* op = g_obox + (size_t)tid * 4;
    op[0] = bx1 + off; op[1] = by1 + off; op[2] = bx2 + off; op[3] = by2 + off;
}

// ---------------------------------------------------------------------------
// Greedy NMS
// ---------------------------------------------------------------------------
#define NMSTH 512
#define NMSLP 7

__global__ void __launch_bounds__(NMSTH) nms_kernel()
{
    int b = blockIdx.x;
    int t = threadIdx.x;

    float sc[NMSLP], ax[NMSLP], ay[NMSLP], bx2[NMSLP], by2[NMSLP], ar[NMSLP];
#pragma unroll
    for (int l = 0; l < NMSLP; l++) {
        int i = t + l * NMSTH;
        if (i < TOTC) {
            sc[l] = g_sc[b * TOTC + i];
            const float* bbp = g_obox + (size_t)(b * TOTC + i) * 4;
            ax[l] = bbp[0]; ay[l] = bbp[1]; bx2[l] = bbp[2]; by2[l] = bbp[3];
            ar[l] = (bx2[l] - ax[l]) * (by2[l] - ay[l]);
        } else {
            sc[l] = -INFINITY; ax[l] = ay[l] = bx2[l] = by2[l] = 0.f; ar[l] = 0.f;
        }
    }

    __shared__ unsigned long long s_best[2];
    __shared__ float bb[6];
    if (t == 0) { s_best[0] = 0ull; s_best[1] = 0ull; }
    __syncthreads();

    for (int it = 0; it < POST; it++) {
        unsigned long long key = 0ull;
#pragma unroll
        for (int l = 0; l < NMSLP; l++) {
            unsigned idx = (unsigned)(t + l * NMSTH);
            unsigned long long kl2 = ((unsigned long long)fkey(sc[l]) << 32)
                                   | (unsigned long long)(0x7FFFFFFFu - idx);
            if (kl2 > key) key = kl2;
        }
#pragma unroll
        for (int o = 16; o; o >>= 1) {
            unsigned long long ok2 = __shfl_down_sync(0xFFFFFFFFu, key, o);
            if (ok2 > key) key = ok2;
        }
        if ((t & 31) == 0) atomicMax(&s_best[it & 1], key);
        __syncthreads();

        unsigned long long bk = s_best[it & 1];
        int j = (int)(0x7FFFFFFFu - (unsigned)(bk & 0xFFFFFFFFull));

        int lo = j - t;
        if (lo >= 0 && (lo & (NMSTH - 1)) == 0) {
            int l = lo >> 9;
            if (l < NMSLP) {
                bb[0] = ax[l]; bb[1] = ay[l]; bb[2] = bx2[l]; bb[3] = by2[l];
                bb[4] = ar[l]; bb[5] = sc[l];
                sc[l] = NEGF;
            }
        }
        if (t == 0) s_best[(it + 1) & 1] = 0ull;
        __syncthreads();

        float jx1 = bb[0], jy1 = bb[1], jx2 = bb[2], jy2 = bb[3], ja = bb[4];
        bool ok = bb[5] > NEGF * 0.5f;
        if (t == 0) {
            float* rr = g_rois + (size_t)(b * POST + it) * 4;
            if (ok) {
                const float* cb = g_box + (size_t)(b * TOTC + j) * 4;
                rr[0] = cb[0]; rr[1] = cb[1]; rr[2] = cb[2]; rr[3] = cb[3];
            } else {
                rr[0] = 0.f; rr[1] = 0.f; rr[2] = 0.f; rr[3] = 0.f;
            }
        }
#pragma unroll
        for (int l = 0; l < NMSLP; l++) {
            float xx1 = fmaxf(jx1, ax[l]),  yy1 = fmaxf(jy1, ay[l]);
            float xx2 = fminf(jx2, bx2[l]), yy2 = fminf(jy2, by2[l]);
            float inter = fmaxf(xx2 - xx1, 0.f) * fmaxf(yy2 - yy1, 0.f);
            float iou = inter / fmaxf(ja + ar[l] - inter, 1e-9f);
            if (iou > 0.7f) sc[l] = NEGF;
        }
    }
}

// ---------------------------------------------------------------------------
// ROI align on feat3 (13x13 channels-last), 7x7 out, sampling 2
// ---------------------------------------------------------------------------
__global__ void __launch_bounds__(256) roi_align_kernel()
{
    int roi = blockIdx.x;
    int b = roi / POST;
    int c = threadIdx.x;

    const float* R = g_rois + (size_t)roi * 4;
    const float scale = 0.015625f;
    float x1 = R[0] * scale - 0.5f, y1 = R[1] * scale - 0.5f;
    float x2 = R[2] * scale - 0.5f, y2 = R[3] * scale - 0.5f;

    float acc[49];
#pragma unroll
    for (int i = 0; i < 49; i++) acc[i] = 0.f;

    const float* F = g_ft3 + (size_t)b * 169 * 256 + c;

#pragma unroll
    for (int py = 0; py < 14; py++) {
        float gy = ((float)py + 0.5f) / 14.0f;
        float yy = y1 + gy * (y2 - y1);
        bool vy = (yy >= -1.0f) && (yy <= 13.0f);
        float y = fminf(fmaxf(yy, 0.f), 12.f);
        int y0 = (int)floorf(y);
        int y1i = min(y0 + 1, 12);
        float ly = y - (float)y0;
#pragma unroll
        for (int px = 0; px < 14; px++) {
            float gx = ((float)px + 0.5f) / 14.0f;
            float xx = x1 + gx * (x2 - x1);
            bool vx = (xx >= -1.0f) && (xx <= 13.0f);
            float x = fminf(fmaxf(xx, 0.f), 12.f);
            int x0 = (int)floorf(x);
            int x1i = min(x0 + 1, 12);
            float lx = x - (float)x0;

            float c00 = __ldg(&F[(y0 * 13 + x0) * 256]);
            float c01 = __ldg(&F[(y0 * 13 + x1i) * 256]);
            float c10 = __ldg(&F[(y1i * 13 + x0) * 256]);
            float c11 = __ldg(&F[(y1i * 13 + x1i) * 256]);
            float v = c00 * (1.f - ly) * (1.f - lx) + c01 * (1.f - ly) * lx
                    + c10 * ly * (1.f - lx)        + c11 * ly * lx;
            if (!(vy && vx)) v = 0.f;
            acc[(py >> 1) * 7 + (px >> 1)] += v;
        }
    }

    float* out = g_rf + (size_t)roi * 12544 + c * 49;
#pragma unroll
    for (int i = 0; i < 49; i++) out[i] = acc[i] * 0.25f;
}

// ---------------------------------------------------------------------------
// FC split-K GEMM (K/4): tile 128(m) x 128(n), 8x8 micro, BK=8 double-buf.
// ---------------------------------------------------------------------------
#define FC_LOAD(k0) do {                                                        \
    if (mval) astg = *(const float4*)(ap + (k0));                               \
    else astg = make_float4(0.f, 0.f, 0.f, 0.f);                                \
    bstg = *(const float4*)(bp + (k0));                                         \
} while (0)

#define FC_STORE(bf) do {                                                       \
    As[bf][ak4 + 0][am] = astg.x; As[bf][ak4 + 1][am] = astg.y;                 \
    As[bf][ak4 + 2][am] = astg.z; As[bf][ak4 + 3][am] = astg.w;                 \
    Bs[bf][ak4 + 0][am] = bstg.x; Bs[bf][ak4 + 1][am] = bstg.y;                 \
    Bs[bf][ak4 + 2][am] = bstg.z; Bs[bf][ak4 + 3][am] = bstg.w;                 \
} while (0)

#define FC_COMPUTE(bf) do {                                                     \
    _Pragma("unroll")                                                           \
    for (int kk = 0; kk < 8; kk++) {                                            \
        float4 a0 = *(const float4*)&As[bf][kk][ty4];                           \
        float4 a1 = *(const float4*)&As[bf][kk][64 + ty4];                      \
        float4 b0 = *(const float4*)&Bs[bf][kk][tx4];                           \
        float4 b1 = *(const float4*)&Bs[bf][kk][64 + tx4];                      \
        float aa[8] = {a0.x, a0.y, a0.z, a0.w, a1.x, a1.y, a1.z, a1.w};         \
        float bbv[8] = {b0.x, b0.y, b0.z, b0.w, b1.x, b1.y, b1.z, b1.w};        \
        _Pragma("unroll")                                                       \
        for (int i2 = 0; i2 < 8; i2++)                                          \
            _Pragma("unroll")                                                   \
            for (int j2 = 0; j2 < 8; j2++)                                      \
                acc[i2][j2] = fmaf(aa[i2], bbv[j2], acc[i2][j2]);               \
    }                                                                           \
} while (0)

__global__ void __launch_bounds__(256, 2) fc_gemm(const float* __restrict__ fw)
{
    __shared__ __align__(16) float As[2][8][132];
    __shared__ __align__(16) float Bs[2][8][132];

    int n0 = blockIdx.x * 128;
    int m0 = blockIdx.y * 128;
    int kidx = blockIdx.z;
    int kbase = kidx * 3136;
    int t = threadIdx.x;

    // load mapping: row am (0..127) of the tile, k-group ak4
    int am  = t >> 1;
    int ak4 = (t & 1) * 4;
    bool mval = (m0 + am) < 600;
    const float* ap = g_rf + (size_t)(mval ? (m0 + am) : 0) * 12544 + kbase + ak4;
    const float* bp = fw   + (size_t)(n0 + am) * 12544 + kbase + ak4;

    int tx4 = (t & 15) * 4;
    int ty4 = (t >> 4) * 4;

    float acc[8][8];
#pragma unroll
    for (int i = 0; i < 8; i++)
#pragma unroll
        for (int j = 0; j < 8; j++) acc[i][j] = 0.f;

    float4 astg, bstg;

    FC_LOAD(0);
    FC_STORE(0);
    __syncthreads();

    int buf = 0;
    for (int k0 = 8; k0 < 3136; k0 += 8) {
        FC_LOAD(k0);
        FC_COMPUTE(buf);
        FC_STORE(buf ^ 1);
        __syncthreads();
        buf ^= 1;
    }
    FC_COMPUTE(buf);

    float* part = g_fcpart + (size_t)kidx * 600 * 1408;
#pragma unroll
    for (int i = 0; i < 8; i++) {
        int m = m0 + ((i < 4) ? (ty4 + i) : (64 + ty4 + i - 4));
        if (m >= 600) continue;
#pragma unroll
        for (int j = 0; j < 8; j++) {
            int n = n0 + ((j < 4) ? (tx4 + j) : (64 + tx4 + j - 4));
            part[(size_t)m * 1408 + n] = acc[i][j];
        }
    }
}

__global__ void fc_reduce(const float* __restrict__ fb, float* __restrict__ out)
{
    int i = blockIdx.x * 256 + threadIdx.x;
    if (i >= 600 * 1408) return;
    const int S = 600 * 1408;
    out[i] = ((g_fcpart[i] + g_fcpart[S + i])
            + (g_fcpart[2 * S + i] + g_fcpart[3 * S + i])) + __ldg(&fb[i % 1408]);
}

// ---------------------------------------------------------------------------
// Launch (conv_all stays at process-launch slot 3 for the ncu capture)
// ---------------------------------------------------------------------------
extern "C" void kernel_launch(void* const* d_in, const int* in_sizes, int n_in,
                              void* d_out, int out_size)
{
    const float* f0     = (const float*)d_in[0];
    const float* f1     = (const float*)d_in[1];
    const float* f2     = (const float*)d_in[2];
    const float* f3     = (const float*)d_in[3];
    const float* conv_w = (const float*)d_in[4];
    const float* conv_b = (const float*)d_in[5];
    const float* cls_w  = (const float*)d_in[6];
    const float* cls_b  = (const float*)d_in[7];
    const float* bbox_w = (const float*)d_in[8];
    const float* bbox_b = (const float*)d_in[9];
    const float* fc_w   = (const float*)d_in[10];
    const float* fc_b   = (const float*)d_in[11];

    prep_wT<<<2304, 256>>>(conv_w);                                   // 0
    prep_ft3<<<(BATCH * 169 * 256 + 255) / 256, 256>>>(f3);           // 1
    zinit<<<(BATCH * POST * 4 + 255) / 256, 256>>>();                 // 2
    conv_all<<<dim3(115, 2, BATCH), 256>>>(f0, f1, f2, f3, conv_b);   // 3  <- profile slot
    head_all<<<dim3(226, BATCH), 256>>>(cls_w, cls_b, bbox_w, bbox_b);// 4
    topk_select<<<8, 512>>>();                                        // 5
    decode_cand<<<(BATCH * TOTC + 255) / 256, 256>>>();               // 6
    nms_kernel<<<BATCH, NMSTH>>>();                                   // 7
    roi_align_kernel<<<BATCH * POST, 256>>>();                        // 8
    fc_gemm<<<dim3(11, 5, 4), 256>>>(fc_w);                           // 9
    fc_reduce<<<(600 * 1408 + 255) / 256, 256>>>(fc_b, (float*)d_out);// 10
}

// round 8
// speedup vs baseline: 2.4991x; 1.5060x over previous
#include <cuda_runtime.h>
#include <cuda_bf16.h>
#include <stdint.h>
#include <math.h>

// ---------------------------------------------------------------------------
// Fixed problem shapes
// ---------------------------------------------------------------------------
#define BATCH 2
#define CHN   256
#define NTOT  43095
#define TOTC  3507
#define POST  300
#define NEGF  (-1e30f)
#define CLAMPF 4.135166556742356f
#define IMG   832.0f

__device__ __constant__ int   c_W[4]      = {104, 52, 26, 13};
__device__ __constant__ int   c_Nanch[4]  = {32448, 8112, 2028, 507};
__device__ __constant__ int   c_noff[4]   = {0, 32448, 40560, 42588};
__device__ __constant__ int   c_K[4]      = {1000, 1000, 1000, 507};
__device__ __constant__ int   c_cbase[4]  = {0, 1000, 2000, 3000};
__device__ __constant__ float c_stride[4] = {8.f, 16.f, 32.f, 64.f};
__device__ __constant__ float c_size[4]   = {32.f, 64.f, 128.f, 256.f};
// 64-px tile prefix per level: {169,43,11,3}
__device__ __constant__ int   c_HTO[4]    = {0, 169, 212, 223};
// g_t per-level float offsets
__device__ __constant__ int   c_toff[4]   = {0, 5537792, 6922240, 7268352};

// ---------------------------------------------------------------------------
// Static device scratch
// ---------------------------------------------------------------------------
__device__ __align__(16) float g_t[7354880];
__device__ __align__(16) float g_ft3[BATCH * 169 * CHN];
__device__ float g_logits[BATCH * NTOT];
__device__ float g_deltas[BATCH * NTOT * 4];
__device__ int   g_cand_n[BATCH * TOTC];
__device__ float g_sc[BATCH * TOTC];
__device__ float g_box[BATCH * TOTC * 4];
__device__ float g_obox[BATCH * TOTC * 4];
__device__ float g_rois[BATCH * POST * 4];
__device__ __align__(16) float g_rf[600 * 12544];
__device__ __align__(16) float g_fcpart[4 * 600 * 1408];
// bf16-split weights. conv: k16-blocked [kblk][co 256][16]; fc: [kblk][m 1408][16]
__device__ __align__(16) __nv_bfloat16 g_cw2_hi[144 * 256 * 16];
__device__ __align__(16) __nv_bfloat16 g_cw2_lo[144 * 256 * 16];
__device__ __align__(16) __nv_bfloat16 g_fw2_hi[784 * 1408 * 16];
__device__ __align__(16) __nv_bfloat16 g_fw2_lo[784 * 1408 * 16];

union U8 { __nv_bfloat16 b[8]; uint4 u; };

__device__ __forceinline__ void bsplit(float x, __nv_bfloat16& h, __nv_bfloat16& l)
{
    h = __float2bfloat16_rn(x);
    l = __float2bfloat16_rn(x - __bfloat162float(h));
}

// ---------------------------------------------------------------------------
// Prep: conv weights -> bf16 hi/lo, k'=tap*256+ci, blocked [k'/16][co][k'%16]
// ---------------------------------------------------------------------------
__global__ void prep_wconv(const float* __restrict__ cw)
{
    int co = blockIdx.x;
    int t = threadIdx.x;
#pragma unroll
    for (int j = 0; j < 9; j++) {
        int kp = j * 256 + t;            // k' = r*256 + ci
        int ci = kp & 255, r = kp >> 8;
        float v = cw[co * 2304 + ci * 9 + r];
        size_t d = (size_t)(kp >> 4) * 4096 + co * 16 + (kp & 15);
        __nv_bfloat16 h, l;
        bsplit(v, h, l);
        g_cw2_hi[d] = h;
        g_cw2_lo[d] = l;
    }
}

// fc weights [1408][12544] -> blocked [k/16][m][k%16] bf16 hi/lo
__global__ void prep_fw(const float* __restrict__ fw)
{
    int base = (blockIdx.x * 256 + threadIdx.x) * 8;
    int m = base / 12544, k = base - m * 12544;
    float4 x0 = *(const float4*)(fw + base);
    float4 x1 = *(const float4*)(fw + base + 4);
    float xs[8] = {x0.x, x0.y, x0.z, x0.w, x1.x, x1.y, x1.z, x1.w};
    U8 hv, lv;
#pragma unroll
    for (int i = 0; i < 8; i++) bsplit(xs[i], hv.b[i], lv.b[i]);
    size_t d = (size_t)(k >> 4) * 22528 + m * 16 + (k & 15);
    *(uint4*)(g_fw2_hi + d) = hv.u;
    *(uint4*)(g_fw2_lo + d) = lv.u;
}

__global__ void prep_ft3(const float* __restrict__ f3)
{
    int idx = blockIdx.x * 256 + threadIdx.x;
    if (idx >= BATCH * 169 * 256) return;
    int c = idx & 255;
    int p = (idx >> 8) % 169;
    int b = idx / (169 * 256);
    g_ft3[idx] = f3[(b * 256 + c) * 169 + p];
}

// ---------------------------------------------------------------------------
// Shared mma machinery: block 128 thr = 4 warps (2M x 2N), tile 128(M) x 64(N),
// warp tile 64x32, BK=16, bf16-split (hi*hi + hi*lo + lo*hi), fp32 accum.
// Smem rows padded to 24 bf16 (48B) -> conflict-free ldmatrix/STS.
// ---------------------------------------------------------------------------
#define LDSM4(r0, r1, r2, r3, addr)                                             \
    asm volatile("ldmatrix.sync.aligned.m8n8.x4.shared.b16 {%0,%1,%2,%3},[%4];" \
                 : "=r"(r0), "=r"(r1), "=r"(r2), "=r"(r3) : "r"(addr))

#define MMA_B16(d, a, b)                                                        \
    asm volatile("mma.sync.aligned.m16n8k16.row.col.f32.bf16.bf16.f32 "         \
                 "{%0,%1,%2,%3},{%4,%5,%6,%7},{%8,%9},{%0,%1,%2,%3};"           \
                 : "+f"(d[0]), "+f"(d[1]), "+f"(d[2]), "+f"(d[3])               \
                 : "r"(a[0]), "r"(a[1]), "r"(a[2]), "r"(a[3]),                  \
                   "r"(b[0]), "r"(b[1]))

#define GEMM_COMPUTE(bf) do {                                                   \
    uint32_t afr[2][4][4];                                                      \
    uint32_t bfr[2][4][2];                                                      \
    _Pragma("unroll")                                                           \
    for (int h = 0; h < 2; h++) {                                               \
        _Pragma("unroll")                                                       \
        for (int mt = 0; mt < 4; mt++) {                                        \
            uint32_t ad = (uint32_t)__cvta_generic_to_shared(                   \
                &Ash[bf][h][mo + mt * 16 + (lane & 15)][(lane >> 4) * 8]);      \
            LDSM4(afr[h][mt][0], afr[h][mt][1], afr[h][mt][2], afr[h][mt][3], ad); \
        }                                                                       \
        _Pragma("unroll")                                                       \
        for (int np = 0; np < 2; np++) {                                        \
            uint32_t bd = (uint32_t)__cvta_generic_to_shared(                   \
                &Bsh[bf][h][no + np * 16 + (lane & 7) + ((lane & 16) >> 1)][lane & 8]); \
            LDSM4(bfr[h][np * 2][0], bfr[h][np * 2][1],                         \
                  bfr[h][np * 2 + 1][0], bfr[h][np * 2 + 1][1], bd);            \
        }                                                                       \
    }                                                                           \
    _Pragma("unroll")                                                           \
    for (int mt = 0; mt < 4; mt++)                                              \
        _Pragma("unroll")                                                       \
        for (int nt = 0; nt < 4; nt++) {                                        \
            MMA_B16(acc[mt][nt], afr[0][mt], bfr[0][nt]);                       \
            MMA_B16(acc[mt][nt], afr[0][mt], bfr[1][nt]);                       \
            MMA_B16(acc[mt][nt], afr[1][mt], bfr[0][nt]);                       \
        }                                                                       \
} while (0)

// ---------------------------------------------------------------------------
// Conv 3x3 (+bias,+ReLU) via mma. K' = tap*256+ci, 144 stages of 16.
// ---------------------------------------------------------------------------
#define CONV_FILL(s, bf) do {                                                   \
    size_t awo = (size_t)(s) * 4096 + (co0 + t) * 16;                           \
    uint4 ah0 = *(const uint4*)(g_cw2_hi + awo);                                \
    uint4 ah1 = *(const uint4*)(g_cw2_hi + awo + 8);                            \
    uint4 al0 = *(const uint4*)(g_cw2_lo + awo);                                \
    uint4 al1 = *(const uint4*)(g_cw2_lo + awo + 8);                            \
    *(uint4*)&Ash[bf][0][t][0] = ah0; *(uint4*)&Ash[bf][0][t][8] = ah1;         \
    *(uint4*)&Ash[bf][1][t][0] = al0; *(uint4*)&Ash[bf][1][t][8] = al1;         \
    int r_ = (s) >> 4;                                                          \
    int dy_ = r_ / 3, dx_ = r_ - 3 * dy_;                                       \
    bool v_ = ((vmy >> dy_) & 1u) && ((vmx >> dx_) & 1u);                       \
    const float* bp_ = inb + (size_t)(((s) & 15) * 16 + kh8) * HW + pbase       \
                           + (dy_ - 1) * W + (dx_ - 1);                         \
    U8 hv, lv;                                                                  \
    _Pragma("unroll")                                                           \
    for (int i_ = 0; i_ < 8; i_++) {                                            \
        float x_ = v_ ? __ldg(bp_ + (size_t)i_ * HW) : 0.f;                     \
        bsplit(x_, hv.b[i_], lv.b[i_]);                                         \
    }                                                                           \
    *(uint4*)&Bsh[bf][0][bpx][kh8] = hv.u;                                      \
    *(uint4*)&Bsh[bf][1][bpx][kh8] = lv.u;                                      \
} while (0)

__global__ void __launch_bounds__(128) conv_all(
    const float* __restrict__ f0, const float* __restrict__ f1,
    const float* __restrict__ f2, const float* __restrict__ f3,
    const float* __restrict__ bias)
{
    __shared__ __align__(16) __nv_bfloat16 Ash[2][2][128][24];
    __shared__ __align__(16) __nv_bfloat16 Bsh[2][2][64][24];

    int bx = blockIdx.x;
    int lvl = (bx < 169) ? 0 : (bx < 212) ? 1 : (bx < 223) ? 2 : 3;
    int p0 = (bx - c_HTO[lvl]) * 64;
    int W  = c_W[lvl];
    int H  = W;
    int Np = W * W;
    int HW = Np;
    const float* in = (lvl == 0) ? f0 : (lvl == 1) ? f1 : (lvl == 2) ? f2 : f3;

    int b   = blockIdx.z;
    int co0 = blockIdx.y * 128;
    int t   = threadIdx.x;
    int lane = t & 31, warp = t >> 5;
    int mo = (warp >> 1) * 64, no = (warp & 1) * 32;

    const float* inb = in + (size_t)b * CHN * HW;

    // B fill geometry: one pixel per (t&63), k-half (t>>6)*8
    int bpx = t & 63;
    int kh8 = (t >> 6) * 8;
    int pix = p0 + bpx;
    bool inp = pix < Np;
    int py = inp ? (pix / W) : 0;
    int px = inp ? (pix - py * W) : 0;
    int pbase = py * W + px;
    unsigned vmy = ((py > 0) ? 1u : 0u) | 2u | ((py + 1 < H) ? 4u : 0u);
    unsigned vmx = ((px > 0) ? 1u : 0u) | 2u | ((px + 1 < W) ? 4u : 0u);
    if (!inp) vmy = 0u;

    float acc[4][4][4];
#pragma unroll
    for (int i = 0; i < 4; i++)
#pragma unroll
        for (int j = 0; j < 4; j++)
#pragma unroll
            for (int q = 0; q < 4; q++) acc[i][j][q] = 0.f;

    CONV_FILL(0, 0);
    __syncthreads();

    int bf = 0;
#pragma unroll 2
    for (int s = 1; s < 144; s++) {
        CONV_FILL(s, bf ^ 1);
        GEMM_COMPUTE(bf);
        __syncthreads();
        bf ^= 1;
    }
    GEMM_COMPUTE(bf);

    // epilogue: bias + ReLU; c frag: d0,d1=(row g, col tg*2,+1), d2,d3=(row g+8)
    int g = lane >> 2, tg = lane & 3;
#pragma unroll
    for (int mt = 0; mt < 4; mt++) {
        int coA = co0 + mo + mt * 16 + g;
        int coB = coA + 8;
        float bA = __ldg(&bias[coA]);
        float bB = __ldg(&bias[coB]);
        float* opA = g_t + c_toff[lvl] + ((size_t)b * CHN + coA) * Np;
        float* opB = g_t + c_toff[lvl] + ((size_t)b * CHN + coB) * Np;
#pragma unroll
        for (int nt = 0; nt < 4; nt++) {
            int pxo = p0 + no + nt * 8 + tg * 2;
            float* d = acc[mt][nt];
            if (pxo < Np) {
                opA[pxo] = fmaxf(d[0] + bA, 0.f);
                opB[pxo] = fmaxf(d[2] + bB, 0.f);
            }
            if (pxo + 1 < Np) {
                opA[pxo + 1] = fmaxf(d[1] + bA, 0.f);
                opB[pxo + 1] = fmaxf(d[3] + bB, 0.f);
            }
        }
    }
}

// ---------------------------------------------------------------------------
// FC via mma: part[kidx][roi][out] = rf @ fw^T (split-K 4), 196 stages each.
// A = fw (M=1408), B^T = rf rows (N=600).
// ---------------------------------------------------------------------------
#define FC_FILL(s, bf) do {                                                     \
    size_t awo = (size_t)(kblk0 + (s)) * 22528 + (m0 + t) * 16;                 \
    uint4 ah0 = *(const uint4*)(g_fw2_hi + awo);                                \
    uint4 ah1 = *(const uint4*)(g_fw2_hi + awo + 8);                            \
    uint4 al0 = *(const uint4*)(g_fw2_lo + awo);                                \
    uint4 al1 = *(const uint4*)(g_fw2_lo + awo + 8);                            \
    *(uint4*)&Ash[bf][0][t][0] = ah0; *(uint4*)&Ash[bf][0][t][8] = ah1;         \
    *(uint4*)&Ash[bf][1][t][0] = al0; *(uint4*)&Ash[bf][1][t][8] = al1;         \
    U8 hv, lv;                                                                  \
    if (nvalid) {                                                               \
        const float* rp_ = g_rf + (size_t)(n0 + bpx) * 12544 + kbase + (s) * 16 + kh8; \
        float4 x0_ = *(const float4*)rp_;                                       \
        float4 x1_ = *(const float4*)(rp_ + 4);                                 \
        float xs_[8] = {x0_.x, x0_.y, x0_.z, x0_.w, x1_.x, x1_.y, x1_.z, x1_.w}; \
        _Pragma("unroll")                                                       \
        for (int i_ = 0; i_ < 8; i_++) bsplit(xs_[i_], hv.b[i_], lv.b[i_]);     \
    } else {                                                                    \
        hv.u = make_uint4(0, 0, 0, 0); lv.u = make_uint4(0, 0, 0, 0);           \
    }                                                                           \
    *(uint4*)&Bsh[bf][0][bpx][kh8] = hv.u;                                      \
    *(uint4*)&Bsh[bf][1][bpx][kh8] = lv.u;                                      \
} while (0)

__global__ void __launch_bounds__(128) fc_gemm()
{
    __shared__ __align__(16) __nv_bfloat16 Ash[2][2][128][24];
    __shared__ __align__(16) __nv_bfloat16 Bsh[2][2][64][24];

    int m0 = blockIdx.x * 128;
    int n0 = blockIdx.y * 64;
    int kidx = blockIdx.z;
    int kbase = kidx * 3136;
    int kblk0 = kidx * 196;
    int t = threadIdx.x;
    int lane = t & 31, warp = t >> 5;
    int mo = (warp >> 1) * 64, no = (warp & 1) * 32;

    int bpx = t & 63;
    int kh8 = (t >> 6) * 8;
    bool nvalid = (n0 + bpx) < 600;

    float acc[4][4][4];
#pragma unroll
    for (int i = 0; i < 4; i++)
#pragma unroll
        for (int j = 0; j < 4; j++)
#pragma unroll
            for (int q = 0; q < 4; q++) acc[i][j][q] = 0.f;

    FC_FILL(0, 0);
    __syncthreads();

    int bf = 0;
#pragma unroll 2
    for (int s = 1; s < 196; s++) {
        FC_FILL(s, bf ^ 1);
        GEMM_COMPUTE(bf);
        __syncthreads();
        bf ^= 1;
    }
    GEMM_COMPUTE(bf);

    int g = lane >> 2, tg = lane & 3;
    float* part = g_fcpart + (size_t)kidx * 600 * 1408;
#pragma unroll
    for (int mt = 0; mt < 4; mt++) {
        int m = m0 + mo + mt * 16 + g;
#pragma unroll
        for (int nt = 0; nt < 4; nt++) {
            int n = n0 + no + nt * 8 + tg * 2;
            float* d = acc[mt][nt];
            if (n < 600) {
                part[(size_t)n * 1408 + m]     = d[0];
                part[(size_t)n * 1408 + m + 8] = d[2];
            }
            if (n + 1 < 600) {
                part[(size_t)(n + 1) * 1408 + m]     = d[1];
                part[(size_t)(n + 1) * 1408 + m + 8] = d[3];
            }
        }
    }
}

__global__ void fc_reduce(const float* __restrict__ fb, float* __restrict__ out)
{
    int i = blockIdx.x * 256 + threadIdx.x;
    if (i >= 600 * 1408) return;
    const int S = 600 * 1408;
    out[i] = ((g_fcpart[i] + g_fcpart[S + i])
            + (g_fcpart[2 * S + i] + g_fcpart[3 * S + i])) + __ldg(&fb[i % 1408]);
}

// ---------------------------------------------------------------------------
// 1x1 heads, all levels: 64 px/block, 4 channel-quarters, smem reduce.
// ---------------------------------------------------------------------------
__global__ void __launch_bounds__(256) head_all(
    const float* __restrict__ cls_w, const float* __restrict__ cls_b,
    const float* __restrict__ bbox_w, const float* __restrict__ bbox_b)
{
    __shared__ float w[15][256];
    __shared__ float red[4][15][65];

    int bx = blockIdx.x;
    int lvl = (bx < 169) ? 0 : (bx < 212) ? 1 : (bx < 223) ? 2 : 3;
    int pt = bx - c_HTO[lvl];
    int Wl = c_W[lvl];
    int Np = Wl * Wl;
    int noff = c_noff[lvl];

    int b = blockIdx.y;
    int t = threadIdx.x;
    for (int i = t; i < 15 * 256; i += 256) {
        int o = i >> 8, c = i & 255;
        w[o][c] = (o < 3) ? cls_w[o * 256 + c] : bbox_w[(o - 3) * 256 + c];
    }
    __syncthreads();

    int pl = t & 63, cq = t >> 6;
    int p = pt * 64 + pl;
    float acc[15];
#pragma unroll
    for (int o = 0; o < 15; o++) acc[o] = 0.f;

    if (p < Np) {
        const float* tb = g_t + c_toff[lvl] + ((size_t)b * CHN + cq * 64) * Np + p;
#pragma unroll 4
        for (int c = 0; c < 64; c++) {
            float v = __ldg(tb + (size_t)c * Np);
#pragma unroll
            for (int o = 0; o < 15; o++) acc[o] = fmaf(w[o][cq * 64 + c], v, acc[o]);
        }
    }
#pragma unroll
    for (int o = 0; o < 15; o++) red[cq][o][pl] = acc[o];
    __syncthreads();

    for (int idx = t; idx < 64 * 15; idx += 256) {
        int pl2 = idx & 63, o = idx >> 6;
        int p2 = pt * 64 + pl2;
        if (p2 >= Np) continue;
        float s = red[0][o][pl2] + red[1][o][pl2] + red[2][o][pl2] + red[3][o][pl2];
        int nb = b * NTOT + noff + p2 * 3;
        if (o < 3) {
            g_logits[nb + o] = s + __ldg(&cls_b[o]);
        } else {
            int oo = o - 3;
            int a = oo >> 2, j = oo & 3;
            g_deltas[(size_t)(nb + a) * 4 + j] = s + __ldg(&bbox_b[oo]);
        }
    }
}

// ---------------------------------------------------------------------------
// Radix top-k select per (batch, level).
// ---------------------------------------------------------------------------
__device__ __forceinline__ unsigned fkey(float f)
{
    unsigned u = __float_as_uint(f);
    return (u & 0x80000000u) ? ~u : (u | 0x80000000u);
}

__global__ void __launch_bounds__(512) topk_select()
{
    int blk = blockIdx.x;
    int b = blk >> 2, lvl = blk & 3;
    int N = c_Nanch[lvl], K = c_K[lvl];
    const float* lg = g_logits + b * NTOT + c_noff[lvl];

    __shared__ unsigned bins[256];
    __shared__ unsigned s_prefix, s_kk, s_cG, s_c1, s_c2;
    int t = threadIdx.x;
    if (t == 0) { s_prefix = 0u; s_kk = (unsigned)K; }
    __syncthreads();

    for (int pass = 3; pass >= 0; pass--) {
        int sh = pass * 8;
        if (t < 256) bins[t] = 0u;
        __syncthreads();
        unsigned prefix = s_prefix;
        unsigned hmask = (pass == 3) ? 0u : (0xFFFFFFFFu << (sh + 8));
        for (int i = t; i < N; i += 512) {
            unsigned key = fkey(lg[i]);
            if ((key & hmask) == prefix)
                atomicAdd(&bins[(key >> sh) & 255u], 1u);
        }
        __syncthreads();
        if (t == 0) {
            unsigned kk = s_kk, cum = 0u;
            int v = 255;
            for (; v > 0; v--) {
                if (cum + bins[v] >= kk) break;
                cum += bins[v];
            }
            s_kk = kk - cum;
            s_prefix = prefix | ((unsigned)v << sh);
        }
        __syncthreads();
    }
    unsigned T = s_prefix;
    if (t == 0) { s_cG = 0u; s_c1 = 0u; s_c2 = 0u; }
    __syncthreads();

    unsigned lc = 0u;
    for (int i = t; i < N; i += 512)
        if (fkey(lg[i]) > T) lc++;
    if (lc) atomicAdd(&s_cG, lc);
    __syncthreads();
    unsigned TG = s_cG;

    int* outn = g_cand_n + b * TOTC + c_cbase[lvl];
    for (int i = t; i < N; i += 512) {
        unsigned key = fkey(lg[i]);
        if (key > T) {
            unsigned s = atomicAdd(&s_c1, 1u);
            outn[s] = i;
        } else if (key == T) {
            unsigned s = TG + atomicAdd(&s_c2, 1u);
            if (s < (unsigned)K) outn[s] = i;
        }
    }
}

// ---------------------------------------------------------------------------
// Decode candidates
// ---------------------------------------------------------------------------
__global__ void __launch_bounds__(256) decode_cand()
{
    int tid = blockIdx.x * 256 + threadIdx.x;
    if (tid >= BATCH * TOTC) return;
    int b = tid / TOTC, c = tid - b * TOTC;
    int lvl = c / 1000; if (lvl > 3) lvl = 3;
    int n = g_cand_n[tid];
    int W = c_W[lvl];
    float stride = c_stride[lvl], size = c_size[lvl];

    int a = n % 3, cell = n / 3;
    int gx = cell % W, gy = cell / W;

    float ratio = (a == 0) ? 0.5f : ((a == 1) ? 1.0f : 2.0f);
    float hr = sqrtf(ratio);
    float wr = 1.0f / hr;
    float ws = wr * size, hs = hr * size;
    float w2 = rintf(ws * 0.5f);
    float h2 = rintf(hs * 0.5f);
    float sx = gx * stride, sy = gy * stride;
    float x1 = sx - w2, y1 = sy - h2, x2 = sx + w2, y2 = sy + h2;

    float wa = x2 - x1, ha = y2 - y1;
    float cxa = x1 + 0.5f * wa, cya = y1 + 0.5f * ha;

    int gi = b * NTOT + c_noff[lvl] + n;
    float score = g_logits[gi];
    const float* d = g_deltas + (size_t)gi * 4;
    float dx = d[0], dy = d[1];
    float dw = fminf(d[2], CLAMPF), dh = fminf(d[3], CLAMPF);
    float cx = dx * wa + cxa, cy = dy * ha + cya;
    float bw = expf(dw) * wa, bh = expf(dh) * ha;
    float bx1 = cx - 0.5f * bw, by1 = cy - 0.5f * bh;
    float bx2 = cx + 0.5f * bw, by2 = cy + 0.5f * bh;
    bx1 = fminf(fmaxf(bx1, 0.f), IMG);
    by1 = fminf(fmaxf(by1, 0.f), IMG);
    bx2 = fminf(fmaxf(bx2, 0.f), IMG);
    by2 = fminf(fmaxf(by2, 0.f), IMG);

    float bws = bx2 - bx1, bhs = by2 - by1;
    bool bad = (bws < 0.001f) || (bhs < 0.001f) || (score < 0.0f);
    g_sc[tid] = bad ? NEGF : score;

    float off = (float)lvl * 4096.0f;
    float* bp = g_box + (size_t)tid * 4;
    bp[0] = bx1; bp[1] = by1; bp[2] = bx2; bp[3] = by2;
    float* op = g_obox + (size_t)tid * 4;
    op[0] = bx1 + off; op[1] = by1 + off; op[2] = bx2 + off; op[3] = by2 + off;
}

// ---------------------------------------------------------------------------
// Greedy NMS
// ---------------------------------------------------------------------------
#define NMSTH 512
#define NMSLP 7

__global__ void __launch_bounds__(NMSTH) nms_kernel()
{
    int b = blockIdx.x;
    int t = threadIdx.x;

    float sc[NMSLP], ax[NMSLP], ay[NMSLP], bx2[NMSLP], by2[NMSLP], ar[NMSLP];
#pragma unroll
    for (int l = 0; l < NMSLP; l++) {
        int i = t + l * NMSTH;
        if (i < TOTC) {
            sc[l] = g_sc[b * TOTC + i];
            const float* bbp = g_obox + (size_t)(b * TOTC + i) * 4;
            ax[l] = bbp[0]; ay[l] = bbp[1]; bx2[l] = bbp[2]; by2[l] = bbp[3];
            ar[l] = (bx2[l] - ax[l]) * (by2[l] - ay[l]);
        } else {
            sc[l] = -INFINITY; ax[l] = ay[l] = bx2[l] = by2[l] = 0.f; ar[l] = 0.f;
        }
    }

    __shared__ unsigned long long s_best[2];
    __shared__ float bb[6];
    if (t == 0) { s_best[0] = 0ull; s_best[1] = 0ull; }
    __syncthreads();

    for (int it = 0; it < POST; it++) {
        unsigned long long key = 0ull;
#pragma unroll
        for (int l = 0; l < NMSLP; l++) {
            unsigned idx = (unsigned)(t + l * NMSTH);
            unsigned long long kl2 = ((unsigned long long)fkey(sc[l]) << 32)
                                   | (unsigned long long)(0x7FFFFFFFu - idx);
            if (kl2 > key) key = kl2;
        }
#pragma unroll
        for (int o = 16; o; o >>= 1) {
            unsigned long long ok2 = __shfl_down_sync(0xFFFFFFFFu, key, o);
            if (ok2 > key) key = ok2;
        }
        if ((t & 31) == 0) atomicMax(&s_best[it & 1], key);
        __syncthreads();

        unsigned long long bk = s_best[it & 1];
        int j = (int)(0x7FFFFFFFu - (unsigned)(bk & 0xFFFFFFFFull));

        int lo = j - t;
        if (lo >= 0 && (lo & (NMSTH - 1)) == 0) {
            int l = lo >> 9;
            if (l < NMSLP) {
                bb[0] = ax[l]; bb[1] = ay[l]; bb[2] = bx2[l]; bb[3] = by2[l];
                bb[4] = ar[l]; bb[5] = sc[l];
                sc[l] = NEGF;
            }
        }
        if (t == 0) s_best[(it + 1) & 1] = 0ull;
        __syncthreads();

        float jx1 = bb[0], jy1 = bb[1], jx2 = bb[2], jy2 = bb[3], ja = bb[4];
        bool ok = bb[5] > NEGF * 0.5f;
        if (t == 0) {
            float* rr = g_rois + (size_t)(b * POST + it) * 4;
            if (ok) {
                const float* cb = g_box + (size_t)(b * TOTC + j) * 4;
                rr[0] = cb[0]; rr[1] = cb[1]; rr[2] = cb[2]; rr[3] = cb[3];
            } else {
                rr[0] = 0.f; rr[1] = 0.f; rr[2] = 0.f; rr[3] = 0.f;
            }
        }
#pragma unroll
        for (int l = 0; l < NMSLP; l++) {
            float xx1 = fmaxf(jx1, ax[l]),  yy1 = fmaxf(jy1, ay[l]);
            float xx2 = fminf(jx2, bx2[l]), yy2 = fminf(jy2, by2[l]);
            float inter = fmaxf(xx2 - xx1, 0.f) * fmaxf(yy2 - yy1, 0.f);
            float iou = inter / fmaxf(ja + ar[l] - inter, 1e-9f);
            if (iou > 0.7f) sc[l] = NEGF;
        }
    }
}

// ---------------------------------------------------------------------------
// ROI align on feat3 (13x13 channels-last), 7x7 out, sampling 2
// ---------------------------------------------------------------------------
__global__ void __launch_bounds__(256) roi_align_kernel()
{
    int roi = blockIdx.x;
    int b = roi / POST;
    int c = threadIdx.x;

    const float* R = g_rois + (size_t)roi * 4;
    const float scale = 0.015625f;
    float x1 = R[0] * scale - 0.5f, y1 = R[1] * scale - 0.5f;
    float x2 = R[2] * scale - 0.5f, y2 = R[3] * scale - 0.5f;

    float acc[49];
#pragma unroll
    for (int i = 0; i < 49; i++) acc[i] = 0.f;

    const float* F = g_ft3 + (size_t)b * 169 * 256 + c;

#pragma unroll
    for (int py = 0; py < 14; py++) {
        float gy = ((float)py + 0.5f) / 14.0f;
        float yy = y1 + gy * (y2 - y1);
        bool vy = (yy >= -1.0f) && (yy <= 13.0f);
        float y = fminf(fmaxf(yy, 0.f), 12.f);
        int y0 = (int)floorf(y);
        int y1i = min(y0 + 1, 12);
        float ly = y - (float)y0;
#pragma unroll
        for (int px = 0; px < 14; px++) {
            float gx = ((float)px + 0.5f) / 14.0f;
            float xx = x1 + gx * (x2 - x1);
            bool vx = (xx >= -1.0f) && (xx <= 13.0f);
            float x = fminf(fmaxf(xx, 0.f), 12.f);
            int x0 = (int)floorf(x);
            int x1i = min(x0 + 1, 12);
            float lx = x - (float)x0;

            float c00 = __ldg(&F[(y0 * 13 + x0) * 256]);
            float c01 = __ldg(&F[(y0 * 13 + x1i) * 256]);
            float c10 = __ldg(&F[(y1i * 13 + x0) * 256]);
            float c11 = __ldg(&F[(y1i * 13 + x1i) * 256]);
            float v = c00 * (1.f - ly) * (1.f - lx) + c01 * (1.f - ly) * lx
                    + c10 * ly * (1.f - lx)        + c11 * ly * lx;
            if (!(vy && vx)) v = 0.f;
            acc[(py >> 1) * 7 + (px >> 1)] += v;
        }
    }

    float* out = g_rf + (size_t)roi * 12544 + c * 49;
#pragma unroll
    for (int i = 0; i < 49; i++) out[i] = acc[i] * 0.25f;
}

// ---------------------------------------------------------------------------
// Launch (conv_all at process-launch slot 3 for the ncu capture)
// ---------------------------------------------------------------------------
extern "C" void kernel_launch(void* const* d_in, const int* in_sizes, int n_in,
                              void* d_out, int out_size)
{
    const float* f0     = (const float*)d_in[0];
    const float* f1     = (const float*)d_in[1];
    const float* f2     = (const float*)d_in[2];
    const float* f3     = (const float*)d_in[3];
    const float* conv_w = (const float*)d_in[4];
    const float* conv_b = (const float*)d_in[5];
    const float* cls_w  = (const float*)d_in[6];
    const float* cls_b  = (const float*)d_in[7];
    const float* bbox_w = (const float*)d_in[8];
    const float* bbox_b = (const float*)d_in[9];
    const float* fc_w   = (const float*)d_in[10];
    const float* fc_b   = (const float*)d_in[11];

    prep_wconv<<<256, 256>>>(conv_w);                                 // 0
    prep_fw<<<8624, 256>>>(fc_w);                                     // 1
    prep_ft3<<<(BATCH * 169 * 256 + 255) / 256, 256>>>(f3);           // 2
    conv_all<<<dim3(226, 2, BATCH), 128>>>(f0, f1, f2, f3, conv_b);   // 3 <- profile
    head_all<<<dim3(226, BATCH), 256>>>(cls_w, cls_b, bbox_w, bbox_b);// 4
    topk_select<<<8, 512>>>();                                        // 5
    decode_cand<<<(BATCH * TOTC + 255) / 256, 256>>>();               // 6
    nms_kernel<<<BATCH, NMSTH>>>();                                   // 7
    roi_align_kernel<<<BATCH * POST, 256>>>();                        // 8
    fc_gemm<<<dim3(11, 10, 4), 128>>>();                              // 9
    fc_reduce<<<(600 * 1408 + 255) / 256, 256>>>(fc_b, (float*)d_out);// 10
}